// round 1
// baseline (speedup 1.0000x reference)
#include <cuda_runtime.h>
#include <math.h>

#define BATCH 512
#define DIM   256
#define NPIX  196
#define HEADS 4
#define KD    16
#define VD    64
#define QKVO  96
#define CH    64          // DIM / HEADS
#define N4    49          // NPIX / 4

// ---------------- device scratch (no allocations allowed) ----------------
__device__ float g_bias[HEADS * NPIX * NPIX];          // materialized attention bias
__device__ float g_pwT[DIM * DIM];                     // proj_w transposed, BN-scale folded
__device__ float g_pt[DIM];                            // proj BN shift
__device__ float g_y[(size_t)BATCH * DIM * NPIX];      // raw head outputs (relu in proj)

// ---------------- kernel 0: bias table + proj weight prep ----------------
__global__ void __launch_bounds__(256) k_pre(
    const float* __restrict__ ab, const int* __restrict__ bidx,
    const float* __restrict__ pw, const float* __restrict__ pg,
    const float* __restrict__ pb, const float* __restrict__ prm,
    const float* __restrict__ prv)
{
    int i = blockIdx.x * 256 + threadIdx.x;
    if (i < HEADS * NPIX * NPIX) {
        int h = i / (NPIX * NPIX);
        int nm = i % (NPIX * NPIX);
        g_bias[i] = ab[h * NPIX + bidx[nm]];
    }
    if (i < DIM) {
        float s = pg[i] * rsqrtf(prv[i] + 1e-5f);
        g_pt[i] = pb[i] - prm[i] * s;
    }
    if (i < DIM * DIM) {
        int o = i >> 8, c = i & 255;
        float s = pg[o] * rsqrtf(prv[o] + 1e-5f);
        g_pwT[c * DIM + o] = pw[i] * s;   // pw[o][c] -> pwT[c][o], scale folded
    }
}

// ---------------- kernel 1: cascaded attention, one CTA per batch ----------------
// smem layout (floats)
#define OFF_WT   0        // 64 x 100 (pitch 100 for bank spread), holds wT[c][o], o<96
#define OFF_FEAT 6400     // 64 x 196 ; aliased as P (49 x 196) in attention phase
#define OFF_K    18944    // 16 x 196
#define OFF_Q    22080    // 16 x 196
#define OFF_V    25216    // 64 x 196
#define OFF_OUT  37760    // 64 x 196 (rows 0..15 double as qtmp pre-dwconv)
#define OFF_QS   50304
#define OFF_QT   50400
#define OFF_DWS  50496
#define OFF_DWT  50512
#define OFF_DWW  50528    // 16 x 25
#define OFF_IL   50928    // 64
#define SMEM_FLOATS 50992
#define SMEM_BYTES  (SMEM_FLOATS * 4)

__global__ void __launch_bounds__(256, 1) k_attn(
    const float* __restrict__ x,
    const float* __restrict__ qkv_w, const float* __restrict__ qkv_g,
    const float* __restrict__ qkv_b, const float* __restrict__ qkv_rm,
    const float* __restrict__ qkv_rv,
    const float* __restrict__ dw_w, const float* __restrict__ dw_g,
    const float* __restrict__ dw_b, const float* __restrict__ dw_rm,
    const float* __restrict__ dw_rv)
{
    extern __shared__ float sm[];
    float* wT   = sm + OFF_WT;
    float* feat = sm + OFF_FEAT;   // also P
    float* kbuf = sm + OFF_K;
    float* qbuf = sm + OFF_Q;
    float* vbuf = sm + OFF_V;
    float* obuf = sm + OFF_OUT;
    float* qs   = sm + OFF_QS;
    float* qt   = sm + OFF_QT;
    float* dws  = sm + OFF_DWS;
    float* dwt  = sm + OFF_DWT;
    float* dww  = sm + OFF_DWW;
    float* invl = sm + OFF_IL;

    const int b = blockIdx.x;
    const int t = threadIdx.x;

    for (int h = 0; h < HEADS; ++h) {
        // ---- phase 0: feat = (h==0 ? chunk0 : prev_out + chunk_h) ----
        {
            const float4* xc = reinterpret_cast<const float4*>(x) + ((size_t)b * DIM + h * CH) * N4;
            float4* f4 = reinterpret_cast<float4*>(feat);
            const float4* o4 = reinterpret_cast<const float4*>(obuf);
            if (h == 0) {
                for (int i = t; i < CH * N4; i += 256) f4[i] = xc[i];
            } else {
                for (int i = t; i < CH * N4; i += 256) {
                    float4 a = xc[i]; float4 c = o4[i];
                    a.x += c.x; a.y += c.y; a.z += c.z; a.w += c.w;
                    f4[i] = a;
                }
            }
        }
        // ---- phase 1: load per-head weights & fold BN params ----
        for (int i = t; i < QKVO * CH; i += 256) {
            int c = i & 63, o = i >> 6;
            wT[c * 100 + o] = qkv_w[h * QKVO * CH + o * CH + c];
        }
        if (t < QKVO) {
            float s = qkv_g[h * QKVO + t] * rsqrtf(qkv_rv[h * QKVO + t] + 1e-5f);
            qs[t] = s;
            qt[t] = qkv_b[h * QKVO + t] - qkv_rm[h * QKVO + t] * s;
        } else if (t < QKVO + KD) {
            int d = t - QKVO;
            float s = dw_g[h * KD + d] * rsqrtf(dw_rv[h * KD + d] + 1e-5f);
            dws[d] = s;
            dwt[d] = dw_b[h * KD + d] - dw_rm[h * KD + d] * s;
        }
        for (int i = t; i < KD * 25; i += 256) dww[i] = dw_w[h * KD * 25 + i];
        __syncthreads();

        // ---- phase 2: QKV GEMM (96x196 = W[96x64] @ feat[64x196]) + BN ----
        {
            const float4* f4 = reinterpret_cast<const float4*>(feat);
            const float4* w4 = reinterpret_cast<const float4*>(wT);
            for (int tile = t; tile < 24 * N4; tile += 256) {
                int ot = tile / N4, nt = tile % N4;
                float acc[4][4];
                #pragma unroll
                for (int i = 0; i < 4; ++i)
                    #pragma unroll
                    for (int j = 0; j < 4; ++j) acc[i][j] = 0.f;
                #pragma unroll 8
                for (int c = 0; c < CH; ++c) {
                    float4 wv = w4[c * 25 + ot];
                    float4 fv = f4[c * N4 + nt];
                    float wa[4] = {wv.x, wv.y, wv.z, wv.w};
                    float fa[4] = {fv.x, fv.y, fv.z, fv.w};
                    #pragma unroll
                    for (int i = 0; i < 4; ++i)
                        #pragma unroll
                        for (int j = 0; j < 4; ++j)
                            acc[i][j] = fmaf(wa[i], fa[j], acc[i][j]);
                }
                #pragma unroll
                for (int i = 0; i < 4; ++i) {
                    int o = ot * 4 + i;
                    float s = qs[o], tt = qt[o];
                    float4 r = make_float4(fmaf(acc[i][0], s, tt), fmaf(acc[i][1], s, tt),
                                           fmaf(acc[i][2], s, tt), fmaf(acc[i][3], s, tt));
                    float4* dst;
                    if (o < KD)            dst = reinterpret_cast<float4*>(obuf) + o * N4;          // qtmp
                    else if (o < 2 * KD)   dst = reinterpret_cast<float4*>(kbuf) + (o - KD) * N4;   // k
                    else                   dst = reinterpret_cast<float4*>(vbuf) + (o - 2 * KD) * N4; // v
                    dst[nt] = r;
                }
            }
        }
        __syncthreads();

        // ---- phase 3: depthwise 5x5 conv on qtmp -> qbuf (+BN, +attn scale 0.25) ----
        for (int i = t; i < KD * NPIX; i += 256) {
            int d = i / NPIX, n = i % NPIX;
            int yy0 = n / 14, xx0 = n % 14;
            const float* qr = obuf + d * NPIX;
            const float* wr = dww + d * 25;
            float s = 0.f;
            #pragma unroll
            for (int dy = -2; dy <= 2; ++dy) {
                int yy = yy0 + dy;
                if ((unsigned)yy < 14u) {
                    #pragma unroll
                    for (int dx = -2; dx <= 2; ++dx) {
                        int xx = xx0 + dx;
                        if ((unsigned)xx < 14u)
                            s = fmaf(wr[(dy + 2) * 5 + (dx + 2)], qr[yy * 14 + xx], s);
                    }
                }
            }
            qbuf[i] = (fmaf(s, dws[d], dwt[d])) * 0.25f;
        }
        __syncthreads();

        // ---- phase 4: attention in 4 row-blocks of 49 ----
        for (int nb = 0; nb < 4; ++nb) {
            const int n0 = nb * 49;
            // 4a: S[r][m] = q.k + bias -> P (feat region)
            {
                float4* P4 = reinterpret_cast<float4*>(feat);
                const float4* k4 = reinterpret_cast<const float4*>(kbuf);
                const float4* b4 = reinterpret_cast<const float4*>(g_bias) + (h * NPIX + n0) * N4;
                for (int id = t; id < 49 * N4; id += 256) {
                    int r = id / N4, m4 = id % N4;
                    float4 acc = b4[r * N4 + m4];
                    #pragma unroll
                    for (int d = 0; d < KD; ++d) {
                        float qd = qbuf[d * NPIX + n0 + r];
                        float4 kv = k4[d * N4 + m4];
                        acc.x = fmaf(qd, kv.x, acc.x);
                        acc.y = fmaf(qd, kv.y, acc.y);
                        acc.z = fmaf(qd, kv.z, acc.z);
                        acc.w = fmaf(qd, kv.w, acc.w);
                    }
                    P4[id] = acc;
                }
            }
            __syncthreads();
            // 4b: softmax per row (one warp per row, unnormalized; 1/sum kept aside)
            {
                int w = t >> 5, lane = t & 31;
                for (int r = w; r < 49; r += 8) {
                    float* Pr = feat + r * NPIX;
                    float mx = -1e30f;
                    for (int m = lane; m < NPIX; m += 32) mx = fmaxf(mx, Pr[m]);
                    #pragma unroll
                    for (int o = 16; o; o >>= 1) mx = fmaxf(mx, __shfl_xor_sync(0xffffffffu, mx, o));
                    float sum = 0.f;
                    for (int m = lane; m < NPIX; m += 32) {
                        float p = __expf(Pr[m] - mx);
                        Pr[m] = p;
                        sum += p;
                    }
                    #pragma unroll
                    for (int o = 16; o; o >>= 1) sum += __shfl_xor_sync(0xffffffffu, sum, o);
                    if (lane == 0) invl[r] = 1.f / sum;
                }
            }
            __syncthreads();
            // 4c: out[d][n] = sum_m P[n][m] * v[d][m]   (warp = 8-d stripe, lane = row)
            {
                int w = t >> 5, lane = t & 31;
                int d0 = w * 8;
                const float4* v4 = reinterpret_cast<const float4*>(vbuf);
                const float4* P4 = reinterpret_cast<const float4*>(feat);
                #pragma unroll
                for (int rg = 0; rg < 2; ++rg) {
                    int r = rg * 32 + lane;
                    if (r < 49) {
                        float acc[8] = {0.f, 0.f, 0.f, 0.f, 0.f, 0.f, 0.f, 0.f};
                        const float4* Pr = P4 + r * N4;
                        for (int m4 = 0; m4 < N4; ++m4) {
                            float4 p = Pr[m4];
                            #pragma unroll
                            for (int j = 0; j < 8; ++j) {
                                float4 vv = v4[(d0 + j) * N4 + m4];
                                float a = acc[j];
                                a = fmaf(p.x, vv.x, a);
                                a = fmaf(p.y, vv.y, a);
                                a = fmaf(p.z, vv.z, a);
                                a = fmaf(p.w, vv.w, a);
                                acc[j] = a;
                            }
                        }
                        float il = invl[r];
                        int n = n0 + r;
                        #pragma unroll
                        for (int j = 0; j < 8; ++j) {
                            float val = acc[j] * il;
                            obuf[(d0 + j) * NPIX + n] = val;   // raw for next head
                            g_y[((size_t)b * DIM + h * CH + d0 + j) * NPIX + n] = val;
                        }
                    }
                }
            }
            __syncthreads();
        }
        // obuf holds this head's output; next iteration consumes it
    }
}

// ---------------- kernel 2: proj GEMM + BN (relu fused into load) ----------------
// grid (512, 8): CTA = one batch x 32-output-channel block
#define PROJ_SMEM ((12544 + 2048) * 4)
__global__ void __launch_bounds__(256) k_proj(float* __restrict__ out)
{
    extern __shared__ float sm[];
    float* y_s = sm;            // 64 x 196
    float* w_s = sm + 12544;    // 64 x 32 (wT[c][o_local])

    const int b = blockIdx.x;
    const int ob = blockIdx.y;      // 32-channel output block
    const int t = threadIdx.x;

    float acc[2][16];
    #pragma unroll
    for (int s = 0; s < 2; ++s)
        #pragma unroll
        for (int i = 0; i < 16; ++i) acc[s][i] = 0.f;

    const int tile0 = t;
    const int tile1 = t + 256;   // valid if < 392

    for (int cb = 0; cb < 4; ++cb) {
        __syncthreads();
        // load y block with relu
        {
            const float4* ysrc = reinterpret_cast<const float4*>(g_y) + ((size_t)b * DIM + cb * 64) * N4;
            float4* yd = reinterpret_cast<float4*>(y_s);
            for (int i = t; i < 64 * N4; i += 256) {
                float4 v = ysrc[i];
                v.x = fmaxf(v.x, 0.f); v.y = fmaxf(v.y, 0.f);
                v.z = fmaxf(v.z, 0.f); v.w = fmaxf(v.w, 0.f);
                yd[i] = v;
            }
        }
        // load weight block wT[c][o_local]
        for (int i = t; i < 2048; i += 256) {
            int c = i >> 5, o = i & 31;
            w_s[i] = g_pwT[(cb * 64 + c) * DIM + ob * 32 + o];
        }
        __syncthreads();

        const float4* y4 = reinterpret_cast<const float4*>(y_s);
        const float4* w4 = reinterpret_cast<const float4*>(w_s);
        #pragma unroll 4
        for (int c = 0; c < 64; ++c) {
            {
                int ot = tile0 / N4, nt = tile0 % N4;   // tile0 < 392 always (t<256)
                float4 wv = w4[c * 8 + ot];
                float4 yv = y4[c * N4 + nt];
                float wa[4] = {wv.x, wv.y, wv.z, wv.w};
                float ya[4] = {yv.x, yv.y, yv.z, yv.w};
                #pragma unroll
                for (int i = 0; i < 4; ++i)
                    #pragma unroll
                    for (int j = 0; j < 4; ++j)
                        acc[0][i * 4 + j] = fmaf(wa[i], ya[j], acc[0][i * 4 + j]);
            }
            if (tile1 < 392) {
                int ot = tile1 / N4, nt = tile1 % N4;
                float4 wv = w4[c * 8 + ot];
                float4 yv = y4[c * N4 + nt];
                float wa[4] = {wv.x, wv.y, wv.z, wv.w};
                float ya[4] = {yv.x, yv.y, yv.z, yv.w};
                #pragma unroll
                for (int i = 0; i < 4; ++i)
                    #pragma unroll
                    for (int j = 0; j < 4; ++j)
                        acc[1][i * 4 + j] = fmaf(wa[i], ya[j], acc[1][i * 4 + j]);
            }
        }
    }

    // epilogue: add BN shift, store
    float4* out4 = reinterpret_cast<float4*>(out);
    #pragma unroll
    for (int s = 0; s < 2; ++s) {
        int tile = t + s * 256;
        if (tile < 392) {
            int ot = tile / N4, nt = tile % N4;
            #pragma unroll
            for (int i = 0; i < 4; ++i) {
                int og = ob * 32 + ot * 4 + i;
                float tt = g_pt[og];
                float4 r = make_float4(acc[s][i * 4 + 0] + tt, acc[s][i * 4 + 1] + tt,
                                       acc[s][i * 4 + 2] + tt, acc[s][i * 4 + 3] + tt);
                out4[((size_t)b * DIM + og) * N4 + nt] = r;
            }
        }
    }
}

// ---------------- launcher ----------------
extern "C" void kernel_launch(void* const* d_in, const int* in_sizes, int n_in,
                              void* d_out, int out_size)
{
    const float* x       = (const float*)d_in[0];
    const float* qkv_w   = (const float*)d_in[1];
    const float* qkv_g   = (const float*)d_in[2];
    const float* qkv_b   = (const float*)d_in[3];
    const float* qkv_rm  = (const float*)d_in[4];
    const float* qkv_rv  = (const float*)d_in[5];
    const float* dw_w    = (const float*)d_in[6];
    const float* dw_g    = (const float*)d_in[7];
    const float* dw_b    = (const float*)d_in[8];
    const float* dw_rm   = (const float*)d_in[9];
    const float* dw_rv   = (const float*)d_in[10];
    const float* proj_w  = (const float*)d_in[11];
    const float* proj_g  = (const float*)d_in[12];
    const float* proj_b  = (const float*)d_in[13];
    const float* proj_rm = (const float*)d_in[14];
    const float* proj_rv = (const float*)d_in[15];
    const float* ab      = (const float*)d_in[16];
    const int*   bidx    = (const int*)d_in[17];
    float* out = (float*)d_out;

    cudaFuncSetAttribute(k_attn, cudaFuncAttributeMaxDynamicSharedMemorySize, SMEM_BYTES);
    cudaFuncSetAttribute(k_proj, cudaFuncAttributeMaxDynamicSharedMemorySize, PROJ_SMEM);

    k_pre<<<(HEADS * NPIX * NPIX + 255) / 256, 256>>>(ab, bidx, proj_w, proj_g, proj_b, proj_rm, proj_rv);
    k_attn<<<BATCH, 256, SMEM_BYTES>>>(x, qkv_w, qkv_g, qkv_b, qkv_rm, qkv_rv,
                                       dw_w, dw_g, dw_b, dw_rm, dw_rv);
    k_proj<<<dim3(BATCH, 8), 256, PROJ_SMEM>>>(out);
}

// round 2
// speedup vs baseline: 1.2308x; 1.2308x over previous
#include <cuda_runtime.h>
#include <math.h>

#define BATCH 512
#define DIM   256
#define NPIX  196
#define HEADS 4
#define KD    16
#define VD    64
#define QKVO  96
#define CH    64
#define N4    49

// ---------------- device scratch ----------------
__device__ float g_bias[HEADS * NPIX * NPIX];
__device__ float g_pwT[DIM * DIM];
__device__ float g_pt[DIM];
__device__ float g_y[(size_t)BATCH * DIM * NPIX];   // relu already applied

// ---------------- kernel 0: prep ----------------
__global__ void __launch_bounds__(256) k_pre(
    const float* __restrict__ ab, const int* __restrict__ bidx,
    const float* __restrict__ pw, const float* __restrict__ pg,
    const float* __restrict__ pb, const float* __restrict__ prm,
    const float* __restrict__ prv)
{
    int i = blockIdx.x * 256 + threadIdx.x;
    if (i < HEADS * NPIX * NPIX) {
        int h = i / (NPIX * NPIX);
        int nm = i % (NPIX * NPIX);
        g_bias[i] = ab[h * NPIX + bidx[nm]];
    }
    if (i < DIM) {
        float s = pg[i] * rsqrtf(prv[i] + 1e-5f);
        g_pt[i] = pb[i] - prm[i] * s;
    }
    if (i < DIM * DIM) {
        int o = i >> 8, c = i & 255;
        float s = pg[o] * rsqrtf(prv[o] + 1e-5f);
        g_pwT[c * DIM + o] = pw[i] * s;
    }
}

// ---------------- kernel 1: cascaded attention (512 threads / CTA) ----------------
#define OFF_WT   0        // 64 x 100
#define OFF_FEAT 6400     // 64 x 196 ; aliased as P (49 x 196)
#define OFF_K    18944    // 16 x 196
#define OFF_Q    22080    // 16 x 196
#define OFF_V    25216    // 64 x 196
#define OFF_OUT  37760    // 64 x 196 (rows 0..15 double as qtmp)
#define OFF_QS   50304
#define OFF_QT   50400
#define OFF_DWS  50496
#define OFF_DWT  50512
#define OFF_DWW  50528    // 16 x 25
#define OFF_IL   50928    // 64
#define SMEM_FLOATS 50992
#define SMEM_BYTES  (SMEM_FLOATS * 4)
#define NT 512

__global__ void __launch_bounds__(NT, 1) k_attn(
    const float* __restrict__ x,
    const float* __restrict__ qkv_w, const float* __restrict__ qkv_g,
    const float* __restrict__ qkv_b, const float* __restrict__ qkv_rm,
    const float* __restrict__ qkv_rv,
    const float* __restrict__ dw_w, const float* __restrict__ dw_g,
    const float* __restrict__ dw_b, const float* __restrict__ dw_rm,
    const float* __restrict__ dw_rv)
{
    extern __shared__ float sm[];
    float* wT   = sm + OFF_WT;
    float* feat = sm + OFF_FEAT;   // also P
    float* kbuf = sm + OFF_K;
    float* qbuf = sm + OFF_Q;
    float* vbuf = sm + OFF_V;
    float* obuf = sm + OFF_OUT;
    float* qs   = sm + OFF_QS;
    float* qt   = sm + OFF_QT;
    float* dws  = sm + OFF_DWS;
    float* dwt  = sm + OFF_DWT;
    float* dww  = sm + OFF_DWW;
    float* invl = sm + OFF_IL;

    const int b = blockIdx.x;
    const int t = threadIdx.x;
    const int w = t >> 5, lane = t & 31;

    for (int h = 0; h < HEADS; ++h) {
        // ---- phase 0: feat = (h==0 ? chunk0 : prev_out + chunk_h) ----
        {
            const float4* xc = reinterpret_cast<const float4*>(x) + ((size_t)b * DIM + h * CH) * N4;
            float4* f4 = reinterpret_cast<float4*>(feat);
            const float4* o4 = reinterpret_cast<const float4*>(obuf);
            if (h == 0) {
                for (int i = t; i < CH * N4; i += NT) f4[i] = xc[i];
            } else {
                for (int i = t; i < CH * N4; i += NT) {
                    float4 a = xc[i]; float4 c = o4[i];
                    a.x += c.x; a.y += c.y; a.z += c.z; a.w += c.w;
                    f4[i] = a;
                }
            }
        }
        // ---- phase 1: weights + BN folding ----
        for (int i = t; i < QKVO * CH; i += NT) {
            int c = i & 63, o = i >> 6;
            wT[c * 100 + o] = qkv_w[h * QKVO * CH + o * CH + c];
        }
        if (t < QKVO) {
            float s = qkv_g[h * QKVO + t] * rsqrtf(qkv_rv[h * QKVO + t] + 1e-5f);
            qs[t] = s;
            qt[t] = qkv_b[h * QKVO + t] - qkv_rm[h * QKVO + t] * s;
        } else if (t < QKVO + KD) {
            int d = t - QKVO;
            float s = dw_g[h * KD + d] * rsqrtf(dw_rv[h * KD + d] + 1e-5f);
            dws[d] = s;
            dwt[d] = dw_b[h * KD + d] - dw_rm[h * KD + d] * s;
        }
        for (int i = t; i < KD * 25; i += NT) dww[i] = dw_w[h * KD * 25 + i];
        __syncthreads();

        // ---- phase 2: QKV GEMM, thread tile 12o x 4n, single pass (392 units) ----
        if (t < 8 * N4) {
            const int ot = t / N4, nt = t % N4;
            const float4* f4 = reinterpret_cast<const float4*>(feat);
            const float4* w4 = reinterpret_cast<const float4*>(wT);
            float acc[12][4];
            #pragma unroll
            for (int i = 0; i < 12; ++i)
                #pragma unroll
                for (int j = 0; j < 4; ++j) acc[i][j] = 0.f;
            #pragma unroll 4
            for (int c = 0; c < CH; ++c) {
                float4 fv = f4[c * N4 + nt];
                float fa[4] = {fv.x, fv.y, fv.z, fv.w};
                #pragma unroll
                for (int g = 0; g < 3; ++g) {
                    float4 wv = w4[c * 25 + ot * 3 + g];
                    float wa[4] = {wv.x, wv.y, wv.z, wv.w};
                    #pragma unroll
                    for (int i = 0; i < 4; ++i)
                        #pragma unroll
                        for (int j = 0; j < 4; ++j)
                            acc[g * 4 + i][j] = fmaf(wa[i], fa[j], acc[g * 4 + i][j]);
                }
            }
            #pragma unroll
            for (int i = 0; i < 12; ++i) {
                int o = ot * 12 + i;
                float s = qs[o], tt = qt[o];
                float4 r = make_float4(fmaf(acc[i][0], s, tt), fmaf(acc[i][1], s, tt),
                                       fmaf(acc[i][2], s, tt), fmaf(acc[i][3], s, tt));
                float4* dst;
                if (o < KD)          dst = reinterpret_cast<float4*>(obuf) + o * N4;
                else if (o < 2 * KD) dst = reinterpret_cast<float4*>(kbuf) + (o - KD) * N4;
                else                 dst = reinterpret_cast<float4*>(vbuf) + (o - 2 * KD) * N4;
                dst[nt] = r;
            }
        }
        __syncthreads();

        // ---- phase 3: depthwise 5x5 conv on qtmp(obuf rows0-15) -> qbuf ----
        for (int i = t; i < KD * NPIX; i += NT) {
            int d = i / NPIX, n = i % NPIX;
            int yy0 = n / 14, xx0 = n % 14;
            const float* qr = obuf + d * NPIX;
            const float* wr = dww + d * 25;
            float s = 0.f;
            #pragma unroll
            for (int dy = -2; dy <= 2; ++dy) {
                int yy = yy0 + dy;
                if ((unsigned)yy < 14u) {
                    #pragma unroll
                    for (int dx = -2; dx <= 2; ++dx) {
                        int xx = xx0 + dx;
                        if ((unsigned)xx < 14u)
                            s = fmaf(wr[(dy + 2) * 5 + (dx + 2)], qr[yy * 14 + xx], s);
                    }
                }
            }
            qbuf[i] = fmaf(s, dws[d], dwt[d]) * 0.25f;
        }
        __syncthreads();

        // ---- phase 4: attention in 4 row-blocks of 49 ----
        for (int nb = 0; nb < 4; ++nb) {
            const int n0 = nb * 49;
            // 4a: S -> P, thread tile 7r x 4m (7x49 = 343 units)
            if (t < 7 * N4) {
                const int rt = t / N4, mt = t % N4;
                const int r0 = rt * 7;
                const float4* k4 = reinterpret_cast<const float4*>(kbuf);
                const float4* b4 = reinterpret_cast<const float4*>(g_bias) + ((size_t)h * NPIX + n0) * N4;
                float4* P4 = reinterpret_cast<float4*>(feat);
                float4 acc[7];
                #pragma unroll
                for (int i = 0; i < 7; ++i) acc[i] = b4[(r0 + i) * N4 + mt];
                #pragma unroll 4
                for (int d = 0; d < KD; ++d) {
                    float4 kv = k4[d * N4 + mt];
                    const float* qp = qbuf + d * NPIX + n0 + r0;
                    #pragma unroll
                    for (int i = 0; i < 7; ++i) {
                        float qd = qp[i];
                        acc[i].x = fmaf(qd, kv.x, acc[i].x);
                        acc[i].y = fmaf(qd, kv.y, acc[i].y);
                        acc[i].z = fmaf(qd, kv.z, acc[i].z);
                        acc[i].w = fmaf(qd, kv.w, acc[i].w);
                    }
                }
                #pragma unroll
                for (int i = 0; i < 7; ++i) P4[(r0 + i) * N4 + mt] = acc[i];
            }
            __syncthreads();
            // 4b: softmax (warp per row), unnormalized; 1/sum to invl
            for (int r = w; r < 49; r += 16) {
                float* Pr = feat + r * NPIX;
                float mx = -1e30f;
                for (int m = lane; m < NPIX; m += 32) mx = fmaxf(mx, Pr[m]);
                #pragma unroll
                for (int o = 16; o; o >>= 1) mx = fmaxf(mx, __shfl_xor_sync(0xffffffffu, mx, o));
                float sum = 0.f;
                for (int m = lane; m < NPIX; m += 32) {
                    float p = __expf(Pr[m] - mx);
                    Pr[m] = p;
                    sum += p;
                }
                #pragma unroll
                for (int o = 16; o; o >>= 1) sum += __shfl_xor_sync(0xffffffffu, sum, o);
                if (lane == 0) invl[r] = 1.f / sum;
            }
            __syncthreads();
            // 4c: out = V @ P^T ; warp = (8-d stripe, row half)
            {
                const int d0 = (w >> 1) * 8;
                const int half = w & 1;
                const int r = half * 25 + lane;
                const int rmax = half ? 24 : 25;
                if (lane < rmax) {
                    const float4* v4 = reinterpret_cast<const float4*>(vbuf);
                    const float4* Pr = reinterpret_cast<const float4*>(feat) + r * N4;
                    float acc[8] = {0.f,0.f,0.f,0.f,0.f,0.f,0.f,0.f};
                    for (int m4 = 0; m4 < N4; ++m4) {
                        float4 p = Pr[m4];
                        #pragma unroll
                        for (int j = 0; j < 8; ++j) {
                            float4 vv = v4[(d0 + j) * N4 + m4];
                            float a = acc[j];
                            a = fmaf(p.x, vv.x, a);
                            a = fmaf(p.y, vv.y, a);
                            a = fmaf(p.z, vv.z, a);
                            a = fmaf(p.w, vv.w, a);
                            acc[j] = a;
                        }
                    }
                    float il = invl[r];
                    int n = n0 + r;
                    #pragma unroll
                    for (int j = 0; j < 8; ++j) {
                        float val = acc[j] * il;
                        obuf[(d0 + j) * NPIX + n] = val;
                        g_y[((size_t)b * DIM + h * CH + d0 + j) * NPIX + n] = fmaxf(val, 0.f);
                    }
                }
            }
            __syncthreads();
        }
    }
}

// ---------------- kernel 2: proj GEMM + BN ----------------
// grid (512, 4): CTA = one batch x 64-output-channel block, 256 threads
#define PROJ_SMEM ((12544 + 4096) * 4)
__global__ void __launch_bounds__(256) k_proj(float* __restrict__ out)
{
    extern __shared__ float sm[];
    float* y_s = sm;            // 64 x 196
    float* w_s = sm + 12544;    // 64c x 64o

    const int b = blockIdx.x;
    const int ob = blockIdx.y;
    const int t = threadIdx.x;

    // unit u = ot*49 + nt, ot in [0,8) (8 o-channels each), nt in [0,49)
    const int u0 = t;
    const int u1 = t + 256;     // valid if < 392
    const int ot0 = u0 / N4, nt0 = u0 % N4;
    const int ot1 = u1 / N4, nt1 = u1 % N4;
    const bool v1 = (u1 < 8 * N4);

    float acc0[8][4], acc1[8][4];
    #pragma unroll
    for (int i = 0; i < 8; ++i)
        #pragma unroll
        for (int j = 0; j < 4; ++j) { acc0[i][j] = 0.f; acc1[i][j] = 0.f; }

    for (int cb = 0; cb < 4; ++cb) {
        __syncthreads();
        {
            const float4* ysrc = reinterpret_cast<const float4*>(g_y) + ((size_t)b * DIM + cb * 64) * N4;
            float4* yd = reinterpret_cast<float4*>(y_s);
            for (int i = t; i < 64 * N4; i += 256) yd[i] = ysrc[i];
            const float4* wsrc = reinterpret_cast<const float4*>(g_pwT);
            float4* wd = reinterpret_cast<float4*>(w_s);
            for (int i = t; i < 1024; i += 256) {
                int c = i >> 4, o4 = i & 15;   // 16 float4 per c-row
                wd[i] = wsrc[((cb * 64 + c) * DIM + ob * 64) / 4 + o4];
            }
        }
        __syncthreads();

        const float4* y4 = reinterpret_cast<const float4*>(y_s);
        const float4* w4 = reinterpret_cast<const float4*>(w_s);
        #pragma unroll 2
        for (int c = 0; c < 64; ++c) {
            {
                float4 yv = y4[c * N4 + nt0];
                float ya[4] = {yv.x, yv.y, yv.z, yv.w};
                #pragma unroll
                for (int g = 0; g < 2; ++g) {
                    float4 wv = w4[c * 16 + ot0 * 2 + g];
                    float wa[4] = {wv.x, wv.y, wv.z, wv.w};
                    #pragma unroll
                    for (int i = 0; i < 4; ++i)
                        #pragma unroll
                        for (int j = 0; j < 4; ++j)
                            acc0[g * 4 + i][j] = fmaf(wa[i], ya[j], acc0[g * 4 + i][j]);
                }
            }
            if (v1) {
                float4 yv = y4[c * N4 + nt1];
                float ya[4] = {yv.x, yv.y, yv.z, yv.w};
                #pragma unroll
                for (int g = 0; g < 2; ++g) {
                    float4 wv = w4[c * 16 + ot1 * 2 + g];
                    float wa[4] = {wv.x, wv.y, wv.z, wv.w};
                    #pragma unroll
                    for (int i = 0; i < 4; ++i)
                        #pragma unroll
                        for (int j = 0; j < 4; ++j)
                            acc1[g * 4 + i][j] = fmaf(wa[i], ya[j], acc1[g * 4 + i][j]);
                }
            }
        }
    }

    float4* out4 = reinterpret_cast<float4*>(out);
    #pragma unroll
    for (int i = 0; i < 8; ++i) {
        int og = ob * 64 + ot0 * 8 + i;
        float tt = g_pt[og];
        out4[((size_t)b * DIM + og) * N4 + nt0] =
            make_float4(acc0[i][0] + tt, acc0[i][1] + tt, acc0[i][2] + tt, acc0[i][3] + tt);
    }
    if (v1) {
        #pragma unroll
        for (int i = 0; i < 8; ++i) {
            int og = ob * 64 + ot1 * 8 + i;
            float tt = g_pt[og];
            out4[((size_t)b * DIM + og) * N4 + nt1] =
                make_float4(acc1[i][0] + tt, acc1[i][1] + tt, acc1[i][2] + tt, acc1[i][3] + tt);
        }
    }
}

// ---------------- launcher ----------------
extern "C" void kernel_launch(void* const* d_in, const int* in_sizes, int n_in,
                              void* d_out, int out_size)
{
    const float* x       = (const float*)d_in[0];
    const float* qkv_w   = (const float*)d_in[1];
    const float* qkv_g   = (const float*)d_in[2];
    const float* qkv_b   = (const float*)d_in[3];
    const float* qkv_rm  = (const float*)d_in[4];
    const float* qkv_rv  = (const float*)d_in[5];
    const float* dw_w    = (const float*)d_in[6];
    const float* dw_g    = (const float*)d_in[7];
    const float* dw_b    = (const float*)d_in[8];
    const float* dw_rm   = (const float*)d_in[9];
    const float* dw_rv   = (const float*)d_in[10];
    const float* proj_w  = (const float*)d_in[11];
    const float* proj_g  = (const float*)d_in[12];
    const float* proj_b  = (const float*)d_in[13];
    const float* proj_rm = (const float*)d_in[14];
    const float* proj_rv = (const float*)d_in[15];
    const float* ab      = (const float*)d_in[16];
    const int*   bidx    = (const int*)d_in[17];
    float* out = (float*)d_out;

    cudaFuncSetAttribute(k_attn, cudaFuncAttributeMaxDynamicSharedMemorySize, SMEM_BYTES);
    cudaFuncSetAttribute(k_proj, cudaFuncAttributeMaxDynamicSharedMemorySize, PROJ_SMEM);

    k_pre<<<(HEADS * NPIX * NPIX + 255) / 256, 256>>>(ab, bidx, proj_w, proj_g, proj_b, proj_rm, proj_rv);
    k_attn<<<BATCH, NT, SMEM_BYTES>>>(x, qkv_w, qkv_g, qkv_b, qkv_rm, qkv_rv,
                                      dw_w, dw_g, dw_b, dw_rm, dw_rv);
    k_proj<<<dim3(BATCH, 4), 256, PROJ_SMEM>>>(out);
}

// round 3
// speedup vs baseline: 1.3057x; 1.0609x over previous
#include <cuda_runtime.h>
#include <math.h>

#define BATCH 512
#define DIM   256
#define NPIX  196
#define HEADS 4
#define KD    16
#define VD    64
#define QKVO  96
#define CH    64
#define N4    49

typedef unsigned long long ull;

// packed fp32x2 FMA (SASS FFMA2) — only reachable via PTX
#define FMA2(d, a, b) asm("fma.rn.f32x2 %0, %1, %2, %0;" : "+l"(d) : "l"(a), "l"(b))
#define PACK2(u, f)   asm("mov.b64 %0, {%1, %1};" : "=l"(u) : "f"(f))
#define UNPACK2(lo, hi, u) asm("mov.b64 {%0, %1}, %2;" : "=f"(lo), "=f"(hi) : "l"(u))

union F4 {
    float4 v;
    ull u[2];
    float f[4];
};

// ---------------- device scratch ----------------
__device__ float g_bias[HEADS * NPIX * NPIX];
__device__ float g_pwT[DIM * DIM];
__device__ float g_pt[DIM];
__device__ float g_y[(size_t)BATCH * DIM * NPIX];   // relu already applied

// ---------------- kernel 0: prep ----------------
__global__ void __launch_bounds__(256) k_pre(
    const float* __restrict__ ab, const int* __restrict__ bidx,
    const float* __restrict__ pw, const float* __restrict__ pg,
    const float* __restrict__ pb, const float* __restrict__ prm,
    const float* __restrict__ prv)
{
    int i = blockIdx.x * 256 + threadIdx.x;
    if (i < HEADS * NPIX * NPIX) {
        int h = i / (NPIX * NPIX);
        int nm = i % (NPIX * NPIX);
        g_bias[i] = ab[h * NPIX + bidx[nm]];
    }
    if (i < DIM) {
        float s = pg[i] * rsqrtf(prv[i] + 1e-5f);
        g_pt[i] = pb[i] - prm[i] * s;
    }
    if (i < DIM * DIM) {
        int o = i >> 8, c = i & 255;
        float s = pg[o] * rsqrtf(prv[o] + 1e-5f);
        g_pwT[c * DIM + o] = pw[i] * s;
    }
}

// ---------------- kernel 1: cascaded attention (512 threads / CTA) ----------------
#define OFF_WT   0        // 64 x 100
#define OFF_FEAT 6400     // 64 x 196 ; aliased as P (49 x 196)
#define OFF_K    18944    // 16 x 196
#define OFF_Q    22080    // 16 x 196
#define OFF_V    25216    // 64 x 196
#define OFF_OUT  37760    // 64 x 196 (rows 0..15 double as qtmp)
#define OFF_QS   50304
#define OFF_QT   50400
#define OFF_DWS  50496
#define OFF_DWT  50512
#define OFF_DWW  50528    // 16 x 25
#define OFF_IL   50928    // 64
#define SMEM_FLOATS 50992
#define SMEM_BYTES  (SMEM_FLOATS * 4)
#define NT 512

__global__ void __launch_bounds__(NT, 1) k_attn(
    const float* __restrict__ x,
    const float* __restrict__ qkv_w, const float* __restrict__ qkv_g,
    const float* __restrict__ qkv_b, const float* __restrict__ qkv_rm,
    const float* __restrict__ qkv_rv,
    const float* __restrict__ dw_w, const float* __restrict__ dw_g,
    const float* __restrict__ dw_b, const float* __restrict__ dw_rm,
    const float* __restrict__ dw_rv)
{
    extern __shared__ float sm[];
    float* wT   = sm + OFF_WT;
    float* feat = sm + OFF_FEAT;   // also P
    float* kbuf = sm + OFF_K;
    float* qbuf = sm + OFF_Q;
    float* vbuf = sm + OFF_V;
    float* obuf = sm + OFF_OUT;
    float* qs   = sm + OFF_QS;
    float* qt   = sm + OFF_QT;
    float* dws  = sm + OFF_DWS;
    float* dwt  = sm + OFF_DWT;
    float* dww  = sm + OFF_DWW;
    float* invl = sm + OFF_IL;

    const int b = blockIdx.x;
    const int t = threadIdx.x;
    const int w = t >> 5, lane = t & 31;

    for (int h = 0; h < HEADS; ++h) {
        // ---- phase 0: feat = (h==0 ? chunk0 : prev_out + chunk_h) ----
        {
            const float4* xc = reinterpret_cast<const float4*>(x) + ((size_t)b * DIM + h * CH) * N4;
            float4* f4 = reinterpret_cast<float4*>(feat);
            const float4* o4 = reinterpret_cast<const float4*>(obuf);
            if (h == 0) {
                for (int i = t; i < CH * N4; i += NT) f4[i] = xc[i];
            } else {
                for (int i = t; i < CH * N4; i += NT) {
                    float4 a = xc[i]; float4 c = o4[i];
                    a.x += c.x; a.y += c.y; a.z += c.z; a.w += c.w;
                    f4[i] = a;
                }
            }
        }
        // ---- phase 1: weights + BN folding ----
        for (int i = t; i < QKVO * CH; i += NT) {
            int c = i & 63, o = i >> 6;
            wT[c * 100 + o] = qkv_w[h * QKVO * CH + o * CH + c];
        }
        if (t < QKVO) {
            float s = qkv_g[h * QKVO + t] * rsqrtf(qkv_rv[h * QKVO + t] + 1e-5f);
            qs[t] = s;
            qt[t] = qkv_b[h * QKVO + t] - qkv_rm[h * QKVO + t] * s;
        } else if (t < QKVO + KD) {
            int d = t - QKVO;
            float s = dw_g[h * KD + d] * rsqrtf(dw_rv[h * KD + d] + 1e-5f);
            dws[d] = s;
            dwt[d] = dw_b[h * KD + d] - dw_rm[h * KD + d] * s;
        }
        for (int i = t; i < KD * 25; i += NT) dww[i] = dw_w[h * KD * 25 + i];
        __syncthreads();

        // ---- phase 2: QKV GEMM, thread tile 12o x 4n, FFMA2 (pair along o) ----
        if (t < 8 * N4) {
            const int ot = t / N4, nt = t % N4;
            const float4* f4 = reinterpret_cast<const float4*>(feat);
            const float4* w4 = reinterpret_cast<const float4*>(wT);
            ull acc[6][4];
            #pragma unroll
            for (int p = 0; p < 6; ++p)
                #pragma unroll
                for (int j = 0; j < 4; ++j) acc[p][j] = 0ull;
            #pragma unroll 4
            for (int c = 0; c < CH; ++c) {
                F4 fv; fv.v = f4[c * N4 + nt];
                ull fp[4];
                #pragma unroll
                for (int j = 0; j < 4; ++j) PACK2(fp[j], fv.f[j]);
                #pragma unroll
                for (int g = 0; g < 3; ++g) {
                    F4 wv; wv.v = w4[c * 25 + ot * 3 + g];
                    #pragma unroll
                    for (int half = 0; half < 2; ++half) {
                        const int p = g * 2 + half;
                        #pragma unroll
                        for (int j = 0; j < 4; ++j)
                            FMA2(acc[p][j], wv.u[half], fp[j]);
                    }
                }
            }
            #pragma unroll
            for (int p = 0; p < 6; ++p) {
                float lo[4], hi[4];
                #pragma unroll
                for (int j = 0; j < 4; ++j) UNPACK2(lo[j], hi[j], acc[p][j]);
                #pragma unroll
                for (int half = 0; half < 2; ++half) {
                    const int o = ot * 12 + p * 2 + half;
                    const float* src = half ? hi : lo;
                    float s = qs[o], tt = qt[o];
                    float4 r = make_float4(fmaf(src[0], s, tt), fmaf(src[1], s, tt),
                                           fmaf(src[2], s, tt), fmaf(src[3], s, tt));
                    float4* dst;
                    if (o < KD)          dst = reinterpret_cast<float4*>(obuf) + o * N4;
                    else if (o < 2 * KD) dst = reinterpret_cast<float4*>(kbuf) + (o - KD) * N4;
                    else                 dst = reinterpret_cast<float4*>(vbuf) + (o - 2 * KD) * N4;
                    dst[nt] = r;
                }
            }
        }
        __syncthreads();

        // ---- phase 3: depthwise 5x5 conv on qtmp(obuf rows0-15) -> qbuf ----
        for (int i = t; i < KD * NPIX; i += NT) {
            int d = i / NPIX, n = i % NPIX;
            int yy0 = n / 14, xx0 = n % 14;
            const float* qr = obuf + d * NPIX;
            const float* wr = dww + d * 25;
            float s = 0.f;
            #pragma unroll
            for (int dy = -2; dy <= 2; ++dy) {
                int yy = yy0 + dy;
                if ((unsigned)yy < 14u) {
                    #pragma unroll
                    for (int dx = -2; dx <= 2; ++dx) {
                        int xx = xx0 + dx;
                        if ((unsigned)xx < 14u)
                            s = fmaf(wr[(dy + 2) * 5 + (dx + 2)], qr[yy * 14 + xx], s);
                    }
                }
            }
            qbuf[i] = fmaf(s, dws[d], dwt[d]) * 0.25f;
        }
        __syncthreads();

        // ---- phase 4: attention in 4 row-blocks of 49 ----
        for (int nb = 0; nb < 4; ++nb) {
            const int n0 = nb * 49;
            // 4a: S -> P, thread tile 7r x 4m, FFMA2 (pair along m)
            if (t < 7 * N4) {
                const int rt = t / N4, mt = t % N4;
                const int r0 = rt * 7;
                const float4* k4 = reinterpret_cast<const float4*>(kbuf);
                const float4* b4 = reinterpret_cast<const float4*>(g_bias) + ((size_t)h * NPIX + n0) * N4;
                float4* P4 = reinterpret_cast<float4*>(feat);
                ull acc[7][2];
                #pragma unroll
                for (int i = 0; i < 7; ++i) {
                    F4 bv; bv.v = b4[(r0 + i) * N4 + mt];
                    acc[i][0] = bv.u[0]; acc[i][1] = bv.u[1];
                }
                #pragma unroll 4
                for (int d = 0; d < KD; ++d) {
                    F4 kv; kv.v = k4[d * N4 + mt];
                    const float* qp = qbuf + d * NPIX + n0 + r0;
                    #pragma unroll
                    for (int i = 0; i < 7; ++i) {
                        ull qq; PACK2(qq, qp[i]);
                        FMA2(acc[i][0], qq, kv.u[0]);
                        FMA2(acc[i][1], qq, kv.u[1]);
                    }
                }
                #pragma unroll
                for (int i = 0; i < 7; ++i) {
                    F4 r; r.u[0] = acc[i][0]; r.u[1] = acc[i][1];
                    P4[(r0 + i) * N4 + mt] = r.v;
                }
            }
            __syncthreads();
            // 4b: softmax (warp per row), unnormalized; 1/sum to invl
            for (int r = w; r < 49; r += 16) {
                float* Pr = feat + r * NPIX;
                float mx = -1e30f;
                for (int m = lane; m < NPIX; m += 32) mx = fmaxf(mx, Pr[m]);
                #pragma unroll
                for (int o = 16; o; o >>= 1) mx = fmaxf(mx, __shfl_xor_sync(0xffffffffu, mx, o));
                float sum = 0.f;
                for (int m = lane; m < NPIX; m += 32) {
                    float p = __expf(Pr[m] - mx);
                    Pr[m] = p;
                    sum += p;
                }
                #pragma unroll
                for (int o = 16; o; o >>= 1) sum += __shfl_xor_sync(0xffffffffu, sum, o);
                if (lane == 0) invl[r] = 1.f / sum;
            }
            __syncthreads();
            // 4c: out = V @ P^T ; warp = (8-d stripe, row half), FFMA2 (pair along m)
            {
                const int d0 = (w >> 1) * 8;
                const int half = w & 1;
                const int r = half * 25 + lane;
                const int rmax = half ? 24 : 25;
                if (lane < rmax) {
                    const float4* v4 = reinterpret_cast<const float4*>(vbuf);
                    const float4* Pr = reinterpret_cast<const float4*>(feat) + r * N4;
                    ull acc[8][2];
                    #pragma unroll
                    for (int j = 0; j < 8; ++j) { acc[j][0] = 0ull; acc[j][1] = 0ull; }
                    for (int m4 = 0; m4 < N4; ++m4) {
                        F4 p; p.v = Pr[m4];
                        #pragma unroll
                        for (int j = 0; j < 8; ++j) {
                            F4 vv; vv.v = v4[(d0 + j) * N4 + m4];
                            FMA2(acc[j][0], p.u[0], vv.u[0]);
                            FMA2(acc[j][1], p.u[1], vv.u[1]);
                        }
                    }
                    float il = invl[r];
                    int n = n0 + r;
                    #pragma unroll
                    for (int j = 0; j < 8; ++j) {
                        float a0, a1, b0, b1;
                        UNPACK2(a0, a1, acc[j][0]);
                        UNPACK2(b0, b1, acc[j][1]);
                        float val = ((a0 + a1) + (b0 + b1)) * il;
                        obuf[(d0 + j) * NPIX + n] = val;
                        g_y[((size_t)b * DIM + h * CH + d0 + j) * NPIX + n] = fmaxf(val, 0.f);
                    }
                }
            }
            __syncthreads();
        }
    }
}

// ---------------- kernel 2: proj GEMM + BN (FFMA2, pair along o) ----------------
// grid (512, 4): CTA = one batch x 64-output-channel block, 256 threads
#define PROJ_SMEM ((12544 + 4096) * 4)
__global__ void __launch_bounds__(256) k_proj(float* __restrict__ out)
{
    extern __shared__ float sm[];
    float* y_s = sm;            // 64 x 196
    float* w_s = sm + 12544;    // 64c x 64o

    const int b = blockIdx.x;
    const int ob = blockIdx.y;
    const int t = threadIdx.x;

    const int u0 = t;
    const int u1 = t + 256;
    const int ot0 = u0 / N4, nt0 = u0 % N4;
    const int ot1 = u1 / N4, nt1 = u1 % N4;
    const bool v1 = (u1 < 8 * N4);

    ull acc0[4][4], acc1[4][4];   // [o-pair][n]
    #pragma unroll
    for (int p = 0; p < 4; ++p)
        #pragma unroll
        for (int j = 0; j < 4; ++j) { acc0[p][j] = 0ull; acc1[p][j] = 0ull; }

    for (int cb = 0; cb < 4; ++cb) {
        __syncthreads();
        {
            const float4* ysrc = reinterpret_cast<const float4*>(g_y) + ((size_t)b * DIM + cb * 64) * N4;
            float4* yd = reinterpret_cast<float4*>(y_s);
            for (int i = t; i < 64 * N4; i += 256) yd[i] = ysrc[i];
            const float4* wsrc = reinterpret_cast<const float4*>(g_pwT);
            float4* wd = reinterpret_cast<float4*>(w_s);
            for (int i = t; i < 1024; i += 256) {
                int c = i >> 4, o4 = i & 15;
                wd[i] = wsrc[((cb * 64 + c) * DIM + ob * 64) / 4 + o4];
            }
        }
        __syncthreads();

        const float4* y4 = reinterpret_cast<const float4*>(y_s);
        const float4* w4 = reinterpret_cast<const float4*>(w_s);
        #pragma unroll 2
        for (int c = 0; c < 64; ++c) {
            {
                F4 yv; yv.v = y4[c * N4 + nt0];
                ull yp[4];
                #pragma unroll
                for (int j = 0; j < 4; ++j) PACK2(yp[j], yv.f[j]);
                #pragma unroll
                for (int g = 0; g < 2; ++g) {
                    F4 wv; wv.v = w4[c * 16 + ot0 * 2 + g];
                    #pragma unroll
                    for (int half = 0; half < 2; ++half) {
                        const int p = g * 2 + half;
                        #pragma unroll
                        for (int j = 0; j < 4; ++j)
                            FMA2(acc0[p][j], wv.u[half], yp[j]);
                    }
                }
            }
            if (v1) {
                F4 yv; yv.v = y4[c * N4 + nt1];
                ull yp[4];
                #pragma unroll
                for (int j = 0; j < 4; ++j) PACK2(yp[j], yv.f[j]);
                #pragma unroll
                for (int g = 0; g < 2; ++g) {
                    F4 wv; wv.v = w4[c * 16 + ot1 * 2 + g];
                    #pragma unroll
                    for (int half = 0; half < 2; ++half) {
                        const int p = g * 2 + half;
                        #pragma unroll
                        for (int j = 0; j < 4; ++j)
                            FMA2(acc1[p][j], wv.u[half], yp[j]);
                    }
                }
            }
        }
    }

    float4* out4 = reinterpret_cast<float4*>(out);
    #pragma unroll
    for (int p = 0; p < 4; ++p) {
        float lo[4], hi[4];
        #pragma unroll
        for (int j = 0; j < 4; ++j) UNPACK2(lo[j], hi[j], acc0[p][j]);
        #pragma unroll
        for (int half = 0; half < 2; ++half) {
            int og = ob * 64 + ot0 * 8 + p * 2 + half;
            float tt = g_pt[og];
            const float* src = half ? hi : lo;
            out4[((size_t)b * DIM + og) * N4 + nt0] =
                make_float4(src[0] + tt, src[1] + tt, src[2] + tt, src[3] + tt);
        }
    }
    if (v1) {
        #pragma unroll
        for (int p = 0; p < 4; ++p) {
            float lo[4], hi[4];
            #pragma unroll
            for (int j = 0; j < 4; ++j) UNPACK2(lo[j], hi[j], acc1[p][j]);
            #pragma unroll
            for (int half = 0; half < 2; ++half) {
                int og = ob * 64 + ot1 * 8 + p * 2 + half;
                float tt = g_pt[og];
                const float* src = half ? hi : lo;
                out4[((size_t)b * DIM + og) * N4 + nt1] =
                    make_float4(src[0] + tt, src[1] + tt, src[2] + tt, src[3] + tt);
            }
        }
    }
}

// ---------------- launcher ----------------
extern "C" void kernel_launch(void* const* d_in, const int* in_sizes, int n_in,
                              void* d_out, int out_size)
{
    const float* x       = (const float*)d_in[0];
    const float* qkv_w   = (const float*)d_in[1];
    const float* qkv_g   = (const float*)d_in[2];
    const float* qkv_b   = (const float*)d_in[3];
    const float* qkv_rm  = (const float*)d_in[4];
    const float* qkv_rv  = (const float*)d_in[5];
    const float* dw_w    = (const float*)d_in[6];
    const float* dw_g    = (const float*)d_in[7];
    const float* dw_b    = (const float*)d_in[8];
    const float* dw_rm   = (const float*)d_in[9];
    const float* dw_rv   = (const float*)d_in[10];
    const float* proj_w  = (const float*)d_in[11];
    const float* proj_g  = (const float*)d_in[12];
    const float* proj_b  = (const float*)d_in[13];
    const float* proj_rm = (const float*)d_in[14];
    const float* proj_rv = (const float*)d_in[15];
    const float* ab      = (const float*)d_in[16];
    const int*   bidx    = (const int*)d_in[17];
    float* out = (float*)d_out;

    cudaFuncSetAttribute(k_attn, cudaFuncAttributeMaxDynamicSharedMemorySize, SMEM_BYTES);
    cudaFuncSetAttribute(k_proj, cudaFuncAttributeMaxDynamicSharedMemorySize, PROJ_SMEM);

    k_pre<<<(HEADS * NPIX * NPIX + 255) / 256, 256>>>(ab, bidx, proj_w, proj_g, proj_b, proj_rm, proj_rv);
    k_attn<<<BATCH, NT, SMEM_BYTES>>>(x, qkv_w, qkv_g, qkv_b, qkv_rm, qkv_rv,
                                      dw_w, dw_g, dw_b, dw_rm, dw_rv);
    k_proj<<<dim3(BATCH, 4), 256, PROJ_SMEM>>>(out);
}

// round 4
// speedup vs baseline: 1.4227x; 1.0895x over previous
#include <cuda_runtime.h>
#include <math.h>

#define BATCH 512
#define DIM   256
#define NPIX  196
#define HEADS 4
#define KD    16
#define VD    64
#define QKVO  96
#define CH    64
#define N4    49

typedef unsigned long long ull;

// packed fp32x2 FMA (SASS FFMA2) — only reachable via PTX
#define FMA2(d, a, b) asm("fma.rn.f32x2 %0, %1, %2, %0;" : "+l"(d) : "l"(a), "l"(b))
#define PACK2(u, f)   asm("mov.b64 %0, {%1, %1};" : "=l"(u) : "f"(f))
#define UNPACK2(lo, hi, u) asm("mov.b64 {%0, %1}, %2;" : "=f"(lo), "=f"(hi) : "l"(u))
#define EX2(d, s)     asm("ex2.approx.f32 %0, %1;" : "=f"(d) : "f"(s))

#define LOG2E 1.4426950408889634f

union F4 {
    float4 v;
    ull u[2];
    float f[4];
};

// ---------------- device scratch ----------------
__device__ float g_bias[HEADS * NPIX * NPIX];       // pre-multiplied by log2(e)
__device__ float g_pwT[DIM * DIM];
__device__ float g_pt[DIM];
__device__ float g_y[(size_t)BATCH * DIM * NPIX];   // relu already applied

// ---------------- kernel 0: prep ----------------
__global__ void __launch_bounds__(256) k_pre(
    const float* __restrict__ ab, const int* __restrict__ bidx,
    const float* __restrict__ pw, const float* __restrict__ pg,
    const float* __restrict__ pb, const float* __restrict__ prm,
    const float* __restrict__ prv)
{
    int i = blockIdx.x * 256 + threadIdx.x;
    if (i < HEADS * NPIX * NPIX) {
        int h = i / (NPIX * NPIX);
        int nm = i % (NPIX * NPIX);
        g_bias[i] = ab[h * NPIX + bidx[nm]] * LOG2E;
    }
    if (i < DIM) {
        float s = pg[i] * rsqrtf(prv[i] + 1e-5f);
        g_pt[i] = pb[i] - prm[i] * s;
    }
    if (i < DIM * DIM) {
        int o = i >> 8, c = i & 255;
        float s = pg[o] * rsqrtf(prv[o] + 1e-5f);
        g_pwT[c * DIM + o] = pw[i] * s;
    }
}

// ---------------- kernel 1: cascaded attention (512 threads / CTA) ----------------
// smem layout (floats). P (98x196) aliases WT+FEAT (both dead in phase 4).
#define OFF_P    0        // 98 x 196 = 19208
#define OFF_WT   0        // 64 x 100 = 6400
#define OFF_FEAT 6400     // 64 x 196 = 12544 (ends 18944)
#define OFF_K    19216    // 16 x 196
#define OFF_Q    22352    // 16 x 196
#define OFF_V    25488    // 64 x 196
#define OFF_OUT  38032    // 64 x 196 (rows 0..15 double as qtmp)
#define OFF_QS   50576
#define OFF_QT   50672
#define OFF_DWS  50768
#define OFF_DWT  50784
#define OFF_DWW  50800    // 16 x 25
#define OFF_IL   51200    // 98
#define SMEM_FLOATS 51304
#define SMEM_BYTES  (SMEM_FLOATS * 4)
#define NT 512

__global__ void __launch_bounds__(NT, 1) k_attn(
    const float* __restrict__ x,
    const float* __restrict__ qkv_w, const float* __restrict__ qkv_g,
    const float* __restrict__ qkv_b, const float* __restrict__ qkv_rm,
    const float* __restrict__ qkv_rv,
    const float* __restrict__ dw_w, const float* __restrict__ dw_g,
    const float* __restrict__ dw_b, const float* __restrict__ dw_rm,
    const float* __restrict__ dw_rv)
{
    extern __shared__ float sm[];
    float* Psm  = sm + OFF_P;
    float* wT   = sm + OFF_WT;
    float* feat = sm + OFF_FEAT;
    float* kbuf = sm + OFF_K;
    float* qbuf = sm + OFF_Q;
    float* vbuf = sm + OFF_V;
    float* obuf = sm + OFF_OUT;
    float* qs   = sm + OFF_QS;
    float* qt   = sm + OFF_QT;
    float* dws  = sm + OFF_DWS;
    float* dwt  = sm + OFF_DWT;
    float* dww  = sm + OFF_DWW;
    float* invl = sm + OFF_IL;

    const int b = blockIdx.x;
    const int t = threadIdx.x;
    const int w = t >> 5, lane = t & 31;

    for (int h = 0; h < HEADS; ++h) {
        // ---- phase 0: feat = (h==0 ? chunk0 : prev_out + chunk_h) ----
        {
            const float4* xc = reinterpret_cast<const float4*>(x) + ((size_t)b * DIM + h * CH) * N4;
            float4* f4 = reinterpret_cast<float4*>(feat);
            const float4* o4 = reinterpret_cast<const float4*>(obuf);
            if (h == 0) {
                for (int i = t; i < CH * N4; i += NT) f4[i] = xc[i];
            } else {
                for (int i = t; i < CH * N4; i += NT) {
                    float4 a = xc[i]; float4 c = o4[i];
                    a.x += c.x; a.y += c.y; a.z += c.z; a.w += c.w;
                    f4[i] = a;
                }
            }
        }
        // ---- phase 1: weights + BN folding ----
        for (int i = t; i < QKVO * CH; i += NT) {
            int c = i & 63, o = i >> 6;
            wT[c * 100 + o] = qkv_w[h * QKVO * CH + o * CH + c];
        }
        if (t < QKVO) {
            float s = qkv_g[h * QKVO + t] * rsqrtf(qkv_rv[h * QKVO + t] + 1e-5f);
            qs[t] = s;
            qt[t] = qkv_b[h * QKVO + t] - qkv_rm[h * QKVO + t] * s;
        } else if (t < QKVO + KD) {
            int d = t - QKVO;
            float s = dw_g[h * KD + d] * rsqrtf(dw_rv[h * KD + d] + 1e-5f);
            dws[d] = s;
            dwt[d] = dw_b[h * KD + d] - dw_rm[h * KD + d] * s;
        }
        for (int i = t; i < KD * 25; i += NT) dww[i] = dw_w[h * KD * 25 + i];
        __syncthreads();

        // ---- phase 2: QKV GEMM, thread tile 12o x 4n, FFMA2 (pair along o) ----
        if (t < 8 * N4) {
            const int ot = t / N4, nt = t % N4;
            const float4* f4 = reinterpret_cast<const float4*>(feat);
            const float4* w4 = reinterpret_cast<const float4*>(wT);
            ull acc[6][4];
            #pragma unroll
            for (int p = 0; p < 6; ++p)
                #pragma unroll
                for (int j = 0; j < 4; ++j) acc[p][j] = 0ull;
            #pragma unroll 4
            for (int c = 0; c < CH; ++c) {
                F4 fv; fv.v = f4[c * N4 + nt];
                ull fp[4];
                #pragma unroll
                for (int j = 0; j < 4; ++j) PACK2(fp[j], fv.f[j]);
                #pragma unroll
                for (int g = 0; g < 3; ++g) {
                    F4 wv; wv.v = w4[c * 25 + ot * 3 + g];
                    #pragma unroll
                    for (int half = 0; half < 2; ++half) {
                        const int p = g * 2 + half;
                        #pragma unroll
                        for (int j = 0; j < 4; ++j)
                            FMA2(acc[p][j], wv.u[half], fp[j]);
                    }
                }
            }
            #pragma unroll
            for (int p = 0; p < 6; ++p) {
                float lo[4], hi[4];
                #pragma unroll
                for (int j = 0; j < 4; ++j) UNPACK2(lo[j], hi[j], acc[p][j]);
                #pragma unroll
                for (int half = 0; half < 2; ++half) {
                    const int o = ot * 12 + p * 2 + half;
                    const float* src = half ? hi : lo;
                    float s = qs[o], tt = qt[o];
                    float4 r = make_float4(fmaf(src[0], s, tt), fmaf(src[1], s, tt),
                                           fmaf(src[2], s, tt), fmaf(src[3], s, tt));
                    float4* dst;
                    if (o < KD)          dst = reinterpret_cast<float4*>(obuf) + o * N4;
                    else if (o < 2 * KD) dst = reinterpret_cast<float4*>(kbuf) + (o - KD) * N4;
                    else                 dst = reinterpret_cast<float4*>(vbuf) + (o - 2 * KD) * N4;
                    dst[nt] = r;
                }
            }
        }
        __syncthreads();

        // ---- phase 3: depthwise 5x5 conv on qtmp(obuf rows0-15) -> qbuf ----
        // output scale folds attention 1/sqrt(KD) AND log2(e)
        for (int i = t; i < KD * NPIX; i += NT) {
            int d = i / NPIX, n = i % NPIX;
            int yy0 = n / 14, xx0 = n % 14;
            const float* qr = obuf + d * NPIX;
            const float* wr = dww + d * 25;
            float s = 0.f;
            #pragma unroll
            for (int dy = -2; dy <= 2; ++dy) {
                int yy = yy0 + dy;
                if ((unsigned)yy < 14u) {
                    #pragma unroll
                    for (int dx = -2; dx <= 2; ++dx) {
                        int xx = xx0 + dx;
                        if ((unsigned)xx < 14u)
                            s = fmaf(wr[(dy + 2) * 5 + (dx + 2)], qr[yy * 14 + xx], s);
                    }
                }
            }
            qbuf[i] = fmaf(s, dws[d], dwt[d]) * (0.25f * LOG2E);
        }
        __syncthreads();

        // ---- phase 4: attention in 2 row-blocks of 98 ----
        for (int np = 0; np < 2; ++np) {
            const int n0 = np * 98;
            // 4a: S -> P (98 x 196), thread tile 7r x 4m, FFMA2 (pair along m)
            {
                const float4* k4 = reinterpret_cast<const float4*>(kbuf);
                const float4* b4 = reinterpret_cast<const float4*>(g_bias) + ((size_t)h * NPIX + n0) * N4;
                float4* P4 = reinterpret_cast<float4*>(Psm);
                for (int tile = t; tile < 14 * N4; tile += NT) {
                    const int rt = tile / N4, mt = tile % N4;
                    const int r0 = rt * 7;
                    ull acc[7][2];
                    #pragma unroll
                    for (int i = 0; i < 7; ++i) {
                        F4 bv; bv.v = b4[(r0 + i) * N4 + mt];
                        acc[i][0] = bv.u[0]; acc[i][1] = bv.u[1];
                    }
                    #pragma unroll 4
                    for (int d = 0; d < KD; ++d) {
                        F4 kv; kv.v = k4[d * N4 + mt];
                        const float* qp = qbuf + d * NPIX + n0 + r0;
                        #pragma unroll
                        for (int i = 0; i < 7; ++i) {
                            ull qq; PACK2(qq, qp[i]);
                            FMA2(acc[i][0], qq, kv.u[0]);
                            FMA2(acc[i][1], qq, kv.u[1]);
                        }
                    }
                    #pragma unroll
                    for (int i = 0; i < 7; ++i) {
                        F4 r; r.u[0] = acc[i][0]; r.u[1] = acc[i][1];
                        P4[(r0 + i) * N4 + mt] = r.v;
                    }
                }
            }
            __syncthreads();
            // 4b: softmax per row (warp per row), base-2 domain, unnormalized
            for (int r = w; r < 98; r += 16) {
                float* Pr = Psm + r * NPIX;
                float mx = -1e30f;
                for (int m = lane; m < NPIX; m += 32) mx = fmaxf(mx, Pr[m]);
                #pragma unroll
                for (int o = 16; o; o >>= 1) mx = fmaxf(mx, __shfl_xor_sync(0xffffffffu, mx, o));
                float sum = 0.f;
                for (int m = lane; m < NPIX; m += 32) {
                    float p; EX2(p, Pr[m] - mx);
                    Pr[m] = p;
                    sum += p;
                }
                #pragma unroll
                for (int o = 16; o; o >>= 1) sum += __shfl_xor_sync(0xffffffffu, sum, o);
                if (lane == 0) invl[r] = 1.f / sum;
            }
            __syncthreads();
            // 4c: out = V @ P^T ; warp = 8-d stripe x 2 rows per lane
            {
                const int s = w >> 1;            // 0..7
                const int g = w & 1;
                const int d0 = s * 8;
                const int lam = g ? 24 : 25;
                const int r1 = (g ? 50 : 0) + lane;
                const int r2 = r1 + lam;
                if (lane < lam) {
                    const float4* v4 = reinterpret_cast<const float4*>(vbuf);
                    const float4* P1 = reinterpret_cast<const float4*>(Psm) + r1 * N4;
                    const float4* P2 = reinterpret_cast<const float4*>(Psm) + r2 * N4;
                    ull acc1[8][2], acc2[8][2];
                    #pragma unroll
                    for (int j = 0; j < 8; ++j) {
                        acc1[j][0] = 0ull; acc1[j][1] = 0ull;
                        acc2[j][0] = 0ull; acc2[j][1] = 0ull;
                    }
                    for (int m4 = 0; m4 < N4; ++m4) {
                        F4 p1; p1.v = P1[m4];
                        F4 p2; p2.v = P2[m4];
                        #pragma unroll
                        for (int j = 0; j < 8; ++j) {
                            F4 vv; vv.v = v4[(d0 + j) * N4 + m4];
                            FMA2(acc1[j][0], p1.u[0], vv.u[0]);
                            FMA2(acc1[j][1], p1.u[1], vv.u[1]);
                            FMA2(acc2[j][0], p2.u[0], vv.u[0]);
                            FMA2(acc2[j][1], p2.u[1], vv.u[1]);
                        }
                    }
                    float il1 = invl[r1], il2 = invl[r2];
                    int nn1 = n0 + r1, nn2 = n0 + r2;
                    float* gy = g_y + ((size_t)b * DIM + h * CH + d0) * NPIX;
                    #pragma unroll
                    for (int j = 0; j < 8; ++j) {
                        float a0, a1, b0, b1;
                        UNPACK2(a0, a1, acc1[j][0]);
                        UNPACK2(b0, b1, acc1[j][1]);
                        float val1 = ((a0 + a1) + (b0 + b1)) * il1;
                        UNPACK2(a0, a1, acc2[j][0]);
                        UNPACK2(b0, b1, acc2[j][1]);
                        float val2 = ((a0 + a1) + (b0 + b1)) * il2;
                        obuf[(d0 + j) * NPIX + nn1] = val1;
                        obuf[(d0 + j) * NPIX + nn2] = val2;
                        gy[j * NPIX + nn1] = fmaxf(val1, 0.f);
                        gy[j * NPIX + nn2] = fmaxf(val2, 0.f);
                    }
                }
            }
            __syncthreads();
        }
    }
}

// ---------------- kernel 2: proj GEMM + BN (FFMA2, pair along o) ----------------
#define PROJ_SMEM ((12544 + 4096) * 4)
__global__ void __launch_bounds__(256) k_proj(float* __restrict__ out)
{
    extern __shared__ float sm[];
    float* y_s = sm;            // 64 x 196
    float* w_s = sm + 12544;    // 64c x 64o

    const int b = blockIdx.x;
    const int ob = blockIdx.y;
    const int t = threadIdx.x;

    const int u0 = t;
    const int u1 = t + 256;
    const int ot0 = u0 / N4, nt0 = u0 % N4;
    const int ot1 = u1 / N4, nt1 = u1 % N4;
    const bool v1 = (u1 < 8 * N4);

    ull acc0[4][4], acc1[4][4];
    #pragma unroll
    for (int p = 0; p < 4; ++p)
        #pragma unroll
        for (int j = 0; j < 4; ++j) { acc0[p][j] = 0ull; acc1[p][j] = 0ull; }

    for (int cb = 0; cb < 4; ++cb) {
        __syncthreads();
        {
            const float4* ysrc = reinterpret_cast<const float4*>(g_y) + ((size_t)b * DIM + cb * 64) * N4;
            float4* yd = reinterpret_cast<float4*>(y_s);
            for (int i = t; i < 64 * N4; i += 256) yd[i] = ysrc[i];
            const float4* wsrc = reinterpret_cast<const float4*>(g_pwT);
            float4* wd = reinterpret_cast<float4*>(w_s);
            for (int i = t; i < 1024; i += 256) {
                int c = i >> 4, o4 = i & 15;
                wd[i] = wsrc[((cb * 64 + c) * DIM + ob * 64) / 4 + o4];
            }
        }
        __syncthreads();

        const float4* y4 = reinterpret_cast<const float4*>(y_s);
        const float4* w4 = reinterpret_cast<const float4*>(w_s);
        #pragma unroll 2
        for (int c = 0; c < 64; ++c) {
            {
                F4 yv; yv.v = y4[c * N4 + nt0];
                ull yp[4];
                #pragma unroll
                for (int j = 0; j < 4; ++j) PACK2(yp[j], yv.f[j]);
                #pragma unroll
                for (int g = 0; g < 2; ++g) {
                    F4 wv; wv.v = w4[c * 16 + ot0 * 2 + g];
                    #pragma unroll
                    for (int half = 0; half < 2; ++half) {
                        const int p = g * 2 + half;
                        #pragma unroll
                        for (int j = 0; j < 4; ++j)
                            FMA2(acc0[p][j], wv.u[half], yp[j]);
                    }
                }
            }
            if (v1) {
                F4 yv; yv.v = y4[c * N4 + nt1];
                ull yp[4];
                #pragma unroll
                for (int j = 0; j < 4; ++j) PACK2(yp[j], yv.f[j]);
                #pragma unroll
                for (int g = 0; g < 2; ++g) {
                    F4 wv; wv.v = w4[c * 16 + ot1 * 2 + g];
                    #pragma unroll
                    for (int half = 0; half < 2; ++half) {
                        const int p = g * 2 + half;
                        #pragma unroll
                        for (int j = 0; j < 4; ++j)
                            FMA2(acc1[p][j], wv.u[half], yp[j]);
                    }
                }
            }
        }
    }

    float4* out4 = reinterpret_cast<float4*>(out);
    #pragma unroll
    for (int p = 0; p < 4; ++p) {
        float lo[4], hi[4];
        #pragma unroll
        for (int j = 0; j < 4; ++j) UNPACK2(lo[j], hi[j], acc0[p][j]);
        #pragma unroll
        for (int half = 0; half < 2; ++half) {
            int og = ob * 64 + ot0 * 8 + p * 2 + half;
            float tt = g_pt[og];
            const float* src = half ? hi : lo;
            out4[((size_t)b * DIM + og) * N4 + nt0] =
                make_float4(src[0] + tt, src[1] + tt, src[2] + tt, src[3] + tt);
        }
    }
    if (v1) {
        #pragma unroll
        for (int p = 0; p < 4; ++p) {
            float lo[4], hi[4];
            #pragma unroll
            for (int j = 0; j < 4; ++j) UNPACK2(lo[j], hi[j], acc1[p][j]);
            #pragma unroll
            for (int half = 0; half < 2; ++half) {
                int og = ob * 64 + ot1 * 8 + p * 2 + half;
                float tt = g_pt[og];
                const float* src = half ? hi : lo;
                out4[((size_t)b * DIM + og) * N4 + nt1] =
                    make_float4(src[0] + tt, src[1] + tt, src[2] + tt, src[3] + tt);
            }
        }
    }
}

// ---------------- launcher ----------------
extern "C" void kernel_launch(void* const* d_in, const int* in_sizes, int n_in,
                              void* d_out, int out_size)
{
    const float* x       = (const float*)d_in[0];
    const float* qkv_w   = (const float*)d_in[1];
    const float* qkv_g   = (const float*)d_in[2];
    const float* qkv_b   = (const float*)d_in[3];
    const float* qkv_rm  = (const float*)d_in[4];
    const float* qkv_rv  = (const float*)d_in[5];
    const float* dw_w    = (const float*)d_in[6];
    const float* dw_g    = (const float*)d_in[7];
    const float* dw_b    = (const float*)d_in[8];
    const float* dw_rm   = (const float*)d_in[9];
    const float* dw_rv   = (const float*)d_in[10];
    const float* proj_w  = (const float*)d_in[11];
    const float* proj_g  = (const float*)d_in[12];
    const float* proj_b  = (const float*)d_in[13];
    const float* proj_rm = (const float*)d_in[14];
    const float* proj_rv = (const float*)d_in[15];
    const float* ab      = (const float*)d_in[16];
    const int*   bidx    = (const int*)d_in[17];
    float* out = (float*)d_out;

    cudaFuncSetAttribute(k_attn, cudaFuncAttributeMaxDynamicSharedMemorySize, SMEM_BYTES);
    cudaFuncSetAttribute(k_proj, cudaFuncAttributeMaxDynamicSharedMemorySize, PROJ_SMEM);

    k_pre<<<(HEADS * NPIX * NPIX + 255) / 256, 256>>>(ab, bidx, proj_w, proj_g, proj_b, proj_rm, proj_rv);
    k_attn<<<BATCH, NT, SMEM_BYTES>>>(x, qkv_w, qkv_g, qkv_b, qkv_rm, qkv_rv,
                                      dw_w, dw_g, dw_b, dw_rm, dw_rv);
    k_proj<<<dim3(BATCH, 4), 256, PROJ_SMEM>>>(out);
}

// round 5
// speedup vs baseline: 1.4514x; 1.0202x over previous
#include <cuda_runtime.h>
#include <math.h>

#define BATCH 512
#define DIM   256
#define NPIX  196
#define HEADS 4
#define KD    16
#define VD    64
#define QKVO  96
#define CH    64
#define N4    49

typedef unsigned long long ull;

// packed fp32x2 FMA (SASS FFMA2) — only reachable via PTX
#define FMA2(d, a, b) asm("fma.rn.f32x2 %0, %1, %2, %0;" : "+l"(d) : "l"(a), "l"(b))
#define PACK2(u, f)   asm("mov.b64 %0, {%1, %1};" : "=l"(u) : "f"(f))
#define UNPACK2(lo, hi, u) asm("mov.b64 {%0, %1}, %2;" : "=f"(lo), "=f"(hi) : "l"(u))
#define EX2(d, s)     asm("ex2.approx.f32 %0, %1;" : "=f"(d) : "f"(s))

#define LOG2E 1.4426950408889634f

union F4 {
    float4 v;
    ull u[2];
    float f[4];
};

// ---------------- device scratch ----------------
__device__ float g_bias[HEADS * NPIX * NPIX];       // pre-multiplied by log2(e)
__device__ float g_pwT[DIM * DIM];
__device__ float g_pt[DIM];
__device__ float g_y[(size_t)BATCH * DIM * NPIX];   // relu already applied

// ---------------- dummy kernels (shift ncu capture slot onto k_attn) ----------------
__global__ void k_nop1() {}
__global__ void k_nop2() {}

// ---------------- kernel 0: prep ----------------
__global__ void __launch_bounds__(256) k_pre(
    const float* __restrict__ ab, const int* __restrict__ bidx,
    const float* __restrict__ pw, const float* __restrict__ pg,
    const float* __restrict__ pb, const float* __restrict__ prm,
    const float* __restrict__ prv)
{
    int i = blockIdx.x * 256 + threadIdx.x;
    if (i < HEADS * NPIX * NPIX) {
        int h = i / (NPIX * NPIX);
        int nm = i % (NPIX * NPIX);
        g_bias[i] = ab[h * NPIX + bidx[nm]] * LOG2E;
    }
    if (i < DIM) {
        float s = pg[i] * rsqrtf(prv[i] + 1e-5f);
        g_pt[i] = pb[i] - prm[i] * s;
    }
    if (i < DIM * DIM) {
        int o = i >> 8, c = i & 255;
        float s = pg[o] * rsqrtf(prv[o] + 1e-5f);
        g_pwT[c * DIM + o] = pw[i] * s;
    }
}

// ---------------- kernel 1: cascaded attention (512 threads / CTA) ----------------
// smem layout (floats). P (98x196) aliases WT+FEAT (both dead in phase 4).
// qbuf holds DUPLICATED pairs (float2 (v,v)) so QK loads LDS.64 without PACK.
#define OFF_P    0        // 98 x 196 = 19208
#define OFF_WT   0        // 64 x 100 = 6400
#define OFF_FEAT 6400     // 64 x 196 = 12544 (ends 18944)
#define OFF_K    19216    // 16 x 196 = 3136
#define OFF_Q    22352    // 16 x 196 x 2 (paired) = 6272
#define OFF_V    28624    // 64 x 196 = 12544
#define OFF_OUT  41168    // 64 x 196 (rows 0..15 double as qtmp)
#define OFF_QS   53712
#define OFF_QT   53808
#define OFF_DWS  53904
#define OFF_DWT  53920
#define OFF_DWW  53936    // 16 x 25
#define OFF_IL   54336    // 98
#define SMEM_FLOATS 54436
#define SMEM_BYTES  (SMEM_FLOATS * 4)
#define NT 512

__global__ void __launch_bounds__(NT, 1) k_attn(
    const float* __restrict__ x,
    const float* __restrict__ qkv_w, const float* __restrict__ qkv_g,
    const float* __restrict__ qkv_b, const float* __restrict__ qkv_rm,
    const float* __restrict__ qkv_rv,
    const float* __restrict__ dw_w, const float* __restrict__ dw_g,
    const float* __restrict__ dw_b, const float* __restrict__ dw_rm,
    const float* __restrict__ dw_rv)
{
    extern __shared__ float sm[];
    float* Psm  = sm + OFF_P;
    float* wT   = sm + OFF_WT;
    float* feat = sm + OFF_FEAT;
    float* kbuf = sm + OFF_K;
    float2* qbuf2 = reinterpret_cast<float2*>(sm + OFF_Q);
    const ull* qbufu = reinterpret_cast<const ull*>(sm + OFF_Q);
    float* vbuf = sm + OFF_V;
    float* obuf = sm + OFF_OUT;
    float* qs   = sm + OFF_QS;
    float* qt   = sm + OFF_QT;
    float* dws  = sm + OFF_DWS;
    float* dwt  = sm + OFF_DWT;
    float* dww  = sm + OFF_DWW;
    float* invl = sm + OFF_IL;

    const int b = blockIdx.x;
    const int t = threadIdx.x;
    const int w = t >> 5, lane = t & 31;

    for (int h = 0; h < HEADS; ++h) {
        // ---- phase 0: feat = (h==0 ? chunk0 : prev_out + chunk_h) ----
        {
            const float4* xc = reinterpret_cast<const float4*>(x) + ((size_t)b * DIM + h * CH) * N4;
            float4* f4 = reinterpret_cast<float4*>(feat);
            const float4* o4 = reinterpret_cast<const float4*>(obuf);
            if (h == 0) {
                for (int i = t; i < CH * N4; i += NT) f4[i] = xc[i];
            } else {
                for (int i = t; i < CH * N4; i += NT) {
                    float4 a = xc[i]; float4 c = o4[i];
                    a.x += c.x; a.y += c.y; a.z += c.z; a.w += c.w;
                    f4[i] = a;
                }
            }
        }
        // ---- phase 1: weights + BN folding ----
        for (int i = t; i < QKVO * CH; i += NT) {
            int c = i & 63, o = i >> 6;
            wT[c * 100 + o] = qkv_w[h * QKVO * CH + o * CH + c];
        }
        if (t < QKVO) {
            float s = qkv_g[h * QKVO + t] * rsqrtf(qkv_rv[h * QKVO + t] + 1e-5f);
            qs[t] = s;
            qt[t] = qkv_b[h * QKVO + t] - qkv_rm[h * QKVO + t] * s;
        } else if (t < QKVO + KD) {
            int d = t - QKVO;
            float s = dw_g[h * KD + d] * rsqrtf(dw_rv[h * KD + d] + 1e-5f);
            dws[d] = s;
            dwt[d] = dw_b[h * KD + d] - dw_rm[h * KD + d] * s;
        }
        for (int i = t; i < KD * 25; i += NT) dww[i] = dw_w[h * KD * 25 + i];
        __syncthreads();

        // ---- phase 2: QKV GEMM, thread tile 12o x 4n, FFMA2 (pair along o) ----
        if (t < 8 * N4) {
            const int ot = t / N4, nt = t % N4;
            const float4* f4 = reinterpret_cast<const float4*>(feat);
            const float4* w4 = reinterpret_cast<const float4*>(wT);
            ull acc[6][4];
            #pragma unroll
            for (int p = 0; p < 6; ++p)
                #pragma unroll
                for (int j = 0; j < 4; ++j) acc[p][j] = 0ull;
            #pragma unroll 4
            for (int c = 0; c < CH; ++c) {
                F4 fv; fv.v = f4[c * N4 + nt];
                ull fp[4];
                #pragma unroll
                for (int j = 0; j < 4; ++j) PACK2(fp[j], fv.f[j]);
                #pragma unroll
                for (int g = 0; g < 3; ++g) {
                    F4 wv; wv.v = w4[c * 25 + ot * 3 + g];
                    #pragma unroll
                    for (int half = 0; half < 2; ++half) {
                        const int p = g * 2 + half;
                        #pragma unroll
                        for (int j = 0; j < 4; ++j)
                            FMA2(acc[p][j], wv.u[half], fp[j]);
                    }
                }
            }
            #pragma unroll
            for (int p = 0; p < 6; ++p) {
                float lo[4], hi[4];
                #pragma unroll
                for (int j = 0; j < 4; ++j) UNPACK2(lo[j], hi[j], acc[p][j]);
                #pragma unroll
                for (int half = 0; half < 2; ++half) {
                    const int o = ot * 12 + p * 2 + half;
                    const float* src = half ? hi : lo;
                    float s = qs[o], tt = qt[o];
                    float4 r = make_float4(fmaf(src[0], s, tt), fmaf(src[1], s, tt),
                                           fmaf(src[2], s, tt), fmaf(src[3], s, tt));
                    float4* dst;
                    if (o < KD)          dst = reinterpret_cast<float4*>(obuf) + o * N4;
                    else if (o < 2 * KD) dst = reinterpret_cast<float4*>(kbuf) + (o - KD) * N4;
                    else                 dst = reinterpret_cast<float4*>(vbuf) + (o - 2 * KD) * N4;
                    dst[nt] = r;
                }
            }
        }
        __syncthreads();

        // ---- phase 3: depthwise 5x5 conv on qtmp(obuf rows0-15) -> qbuf (paired) ----
        for (int i = t; i < KD * NPIX; i += NT) {
            int d = i / NPIX, n = i % NPIX;
            int yy0 = n / 14, xx0 = n % 14;
            const float* qr = obuf + d * NPIX;
            const float* wr = dww + d * 25;
            float s = 0.f;
            #pragma unroll
            for (int dy = -2; dy <= 2; ++dy) {
                int yy = yy0 + dy;
                if ((unsigned)yy < 14u) {
                    #pragma unroll
                    for (int dx = -2; dx <= 2; ++dx) {
                        int xx = xx0 + dx;
                        if ((unsigned)xx < 14u)
                            s = fmaf(wr[(dy + 2) * 5 + (dx + 2)], qr[yy * 14 + xx], s);
                    }
                }
            }
            float v = fmaf(s, dws[d], dwt[d]) * (0.25f * LOG2E);
            qbuf2[i] = make_float2(v, v);
        }
        __syncthreads();

        // ---- phase 4: attention in 2 row-blocks of 98 ----
        for (int np = 0; np < 2; ++np) {
            const int n0 = np * 98;
            // 4a: S -> P (98 x 196), thread tile 7r x 4m, FFMA2 (pair along m)
            {
                const float4* k4 = reinterpret_cast<const float4*>(kbuf);
                const float4* b4 = reinterpret_cast<const float4*>(g_bias) + ((size_t)h * NPIX + n0) * N4;
                float4* P4 = reinterpret_cast<float4*>(Psm);
                for (int tile = t; tile < 14 * N4; tile += NT) {
                    const int rt = tile / N4, mt = tile % N4;
                    const int r0 = rt * 7;
                    ull acc[7][2];
                    #pragma unroll
                    for (int i = 0; i < 7; ++i) {
                        F4 bv; bv.v = b4[(r0 + i) * N4 + mt];
                        acc[i][0] = bv.u[0]; acc[i][1] = bv.u[1];
                    }
                    #pragma unroll 4
                    for (int d = 0; d < KD; ++d) {
                        F4 kv; kv.v = k4[d * N4 + mt];
                        const ull* qp = qbufu + d * NPIX + n0 + r0;
                        #pragma unroll
                        for (int i = 0; i < 7; ++i) {
                            ull qq = qp[i];
                            FMA2(acc[i][0], qq, kv.u[0]);
                            FMA2(acc[i][1], qq, kv.u[1]);
                        }
                    }
                    #pragma unroll
                    for (int i = 0; i < 7; ++i) {
                        F4 r; r.u[0] = acc[i][0]; r.u[1] = acc[i][1];
                        P4[(r0 + i) * N4 + mt] = r.v;
                    }
                }
            }
            __syncthreads();
            // 4b: softmax per row (warp per row), base-2 domain, unnormalized
            for (int r = w; r < 98; r += 16) {
                float* Pr = Psm + r * NPIX;
                float mx = -1e30f;
                for (int m = lane; m < NPIX; m += 32) mx = fmaxf(mx, Pr[m]);
                #pragma unroll
                for (int o = 16; o; o >>= 1) mx = fmaxf(mx, __shfl_xor_sync(0xffffffffu, mx, o));
                float sum = 0.f;
                for (int m = lane; m < NPIX; m += 32) {
                    float p; EX2(p, Pr[m] - mx);
                    Pr[m] = p;
                    sum += p;
                }
                #pragma unroll
                for (int o = 16; o; o >>= 1) sum += __shfl_xor_sync(0xffffffffu, sum, o);
                if (lane == 0) invl[r] = 1.f / sum;
            }
            __syncthreads();
            // 4c: out = V @ P^T ; warp = 8-d stripe x 2 rows per lane
            {
                const int s = w >> 1;
                const int g = w & 1;
                const int d0 = s * 8;
                const int lam = g ? 24 : 25;
                const int r1 = (g ? 50 : 0) + lane;
                const int r2 = r1 + lam;
                if (lane < lam) {
                    const float4* v4 = reinterpret_cast<const float4*>(vbuf);
                    const float4* P1 = reinterpret_cast<const float4*>(Psm) + r1 * N4;
                    const float4* P2 = reinterpret_cast<const float4*>(Psm) + r2 * N4;
                    ull acc1[8][2], acc2[8][2];
                    #pragma unroll
                    for (int j = 0; j < 8; ++j) {
                        acc1[j][0] = 0ull; acc1[j][1] = 0ull;
                        acc2[j][0] = 0ull; acc2[j][1] = 0ull;
                    }
                    for (int m4 = 0; m4 < N4; ++m4) {
                        F4 p1; p1.v = P1[m4];
                        F4 p2; p2.v = P2[m4];
                        #pragma unroll
                        for (int j = 0; j < 8; ++j) {
                            F4 vv; vv.v = v4[(d0 + j) * N4 + m4];
                            FMA2(acc1[j][0], p1.u[0], vv.u[0]);
                            FMA2(acc1[j][1], p1.u[1], vv.u[1]);
                            FMA2(acc2[j][0], p2.u[0], vv.u[0]);
                            FMA2(acc2[j][1], p2.u[1], vv.u[1]);
                        }
                    }
                    float il1 = invl[r1], il2 = invl[r2];
                    int nn1 = n0 + r1, nn2 = n0 + r2;
                    float* gy = g_y + ((size_t)b * DIM + h * CH + d0) * NPIX;
                    #pragma unroll
                    for (int j = 0; j < 8; ++j) {
                        float a0, a1, b0, b1;
                        UNPACK2(a0, a1, acc1[j][0]);
                        UNPACK2(b0, b1, acc1[j][1]);
                        float val1 = ((a0 + a1) + (b0 + b1)) * il1;
                        UNPACK2(a0, a1, acc2[j][0]);
                        UNPACK2(b0, b1, acc2[j][1]);
                        float val2 = ((a0 + a1) + (b0 + b1)) * il2;
                        obuf[(d0 + j) * NPIX + nn1] = val1;
                        obuf[(d0 + j) * NPIX + nn2] = val2;
                        gy[j * NPIX + nn1] = fmaxf(val1, 0.f);
                        gy[j * NPIX + nn2] = fmaxf(val2, 0.f);
                    }
                }
            }
            __syncthreads();
        }
    }
}

// ---------------- kernel 2: proj GEMM + BN (vertical tile pair shares y) ----------------
#define PROJ_SMEM ((12544 + 4096) * 4)
__global__ void __launch_bounds__(256) k_proj(float* __restrict__ out)
{
    extern __shared__ float sm[];
    float* y_s = sm;            // 64 x 196
    float* w_s = sm + 12544;    // 64c x 64o

    const int b = blockIdx.x;
    const int ob = blockIdx.y;
    const int t = threadIdx.x;

    const bool act = (t < 4 * N4);
    const int ot0 = t / N4, nt = t % N4;

    ull acc0[4][4], acc1[4][4];
    #pragma unroll
    for (int p = 0; p < 4; ++p)
        #pragma unroll
        for (int j = 0; j < 4; ++j) { acc0[p][j] = 0ull; acc1[p][j] = 0ull; }

    for (int cb = 0; cb < 4; ++cb) {
        __syncthreads();
        {
            const float4* ysrc = reinterpret_cast<const float4*>(g_y) + ((size_t)b * DIM + cb * 64) * N4;
            float4* yd = reinterpret_cast<float4*>(y_s);
            for (int i = t; i < 64 * N4; i += 256) yd[i] = ysrc[i];
            const float4* wsrc = reinterpret_cast<const float4*>(g_pwT);
            float4* wd = reinterpret_cast<float4*>(w_s);
            for (int i = t; i < 1024; i += 256) {
                int c = i >> 4, o4 = i & 15;
                wd[i] = wsrc[((cb * 64 + c) * DIM + ob * 64) / 4 + o4];
            }
        }
        __syncthreads();

        if (act) {
            const float4* y4 = reinterpret_cast<const float4*>(y_s);
            const float4* w4 = reinterpret_cast<const float4*>(w_s);
            #pragma unroll 2
            for (int c = 0; c < 64; ++c) {
                F4 yv; yv.v = y4[c * N4 + nt];
                ull yp[4];
                #pragma unroll
                for (int j = 0; j < 4; ++j) PACK2(yp[j], yv.f[j]);
                #pragma unroll
                for (int g = 0; g < 2; ++g) {
                    F4 wv0; wv0.v = w4[c * 16 + ot0 * 2 + g];
                    F4 wv1; wv1.v = w4[c * 16 + (ot0 + 4) * 2 + g];
                    #pragma unroll
                    for (int half = 0; half < 2; ++half) {
                        const int p = g * 2 + half;
                        #pragma unroll
                        for (int j = 0; j < 4; ++j) {
                            FMA2(acc0[p][j], wv0.u[half], yp[j]);
                            FMA2(acc1[p][j], wv1.u[half], yp[j]);
                        }
                    }
                }
            }
        }
    }

    if (act) {
        float4* out4 = reinterpret_cast<float4*>(out);
        #pragma unroll
        for (int p = 0; p < 4; ++p) {
            float lo[4], hi[4];
            #pragma unroll
            for (int j = 0; j < 4; ++j) UNPACK2(lo[j], hi[j], acc0[p][j]);
            #pragma unroll
            for (int half = 0; half < 2; ++half) {
                int og = ob * 64 + ot0 * 8 + p * 2 + half;
                float tt = g_pt[og];
                const float* src = half ? hi : lo;
                out4[((size_t)b * DIM + og) * N4 + nt] =
                    make_float4(src[0] + tt, src[1] + tt, src[2] + tt, src[3] + tt);
            }
        }
        #pragma unroll
        for (int p = 0; p < 4; ++p) {
            float lo[4], hi[4];
            #pragma unroll
            for (int j = 0; j < 4; ++j) UNPACK2(lo[j], hi[j], acc1[p][j]);
            #pragma unroll
            for (int half = 0; half < 2; ++half) {
                int og = ob * 64 + (ot0 + 4) * 8 + p * 2 + half;
                float tt = g_pt[og];
                const float* src = half ? hi : lo;
                out4[((size_t)b * DIM + og) * N4 + nt] =
                    make_float4(src[0] + tt, src[1] + tt, src[2] + tt, src[3] + tt);
            }
        }
    }
}

// ---------------- launcher ----------------
extern "C" void kernel_launch(void* const* d_in, const int* in_sizes, int n_in,
                              void* d_out, int out_size)
{
    const float* x       = (const float*)d_in[0];
    const float* qkv_w   = (const float*)d_in[1];
    const float* qkv_g   = (const float*)d_in[2];
    const float* qkv_b   = (const float*)d_in[3];
    const float* qkv_rm  = (const float*)d_in[4];
    const float* qkv_rv  = (const float*)d_in[5];
    const float* dw_w    = (const float*)d_in[6];
    const float* dw_g    = (const float*)d_in[7];
    const float* dw_b    = (const float*)d_in[8];
    const float* dw_rm   = (const float*)d_in[9];
    const float* dw_rv   = (const float*)d_in[10];
    const float* proj_w  = (const float*)d_in[11];
    const float* proj_g  = (const float*)d_in[12];
    const float* proj_b  = (const float*)d_in[13];
    const float* proj_rm = (const float*)d_in[14];
    const float* proj_rv = (const float*)d_in[15];
    const float* ab      = (const float*)d_in[16];
    const int*   bidx    = (const int*)d_in[17];
    float* out = (float*)d_out;

    cudaFuncSetAttribute(k_attn, cudaFuncAttributeMaxDynamicSharedMemorySize, SMEM_BYTES);
    cudaFuncSetAttribute(k_proj, cudaFuncAttributeMaxDynamicSharedMemorySize, PROJ_SMEM);

    k_nop1<<<1, 32>>>();
    k_nop2<<<1, 32>>>();
    k_pre<<<(HEADS * NPIX * NPIX + 255) / 256, 256>>>(ab, bidx, proj_w, proj_g, proj_b, proj_rm, proj_rv);
    k_attn<<<BATCH, NT, SMEM_BYTES>>>(x, qkv_w, qkv_g, qkv_b, qkv_rm, qkv_rv,
                                      dw_w, dw_g, dw_b, dw_rm, dw_rv);
    k_proj<<<dim3(BATCH, 4), 256, PROJ_SMEM>>>(out);
}

// round 6
// speedup vs baseline: 1.4638x; 1.0085x over previous
#include <cuda_runtime.h>
#include <math.h>

#define BATCH 512
#define DIM   256
#define NPIX  196
#define HEADS 4
#define KD    16
#define VD    64
#define QKVO  96
#define CH    64
#define N4    49

typedef unsigned long long ull;

// packed fp32x2 FMA (SASS FFMA2) — only reachable via PTX
#define FMA2(d, a, b) asm("fma.rn.f32x2 %0, %1, %2, %0;" : "+l"(d) : "l"(a), "l"(b))
#define PACK2(u, f)   asm("mov.b64 %0, {%1, %1};" : "=l"(u) : "f"(f))
#define UNPACK2(lo, hi, u) asm("mov.b64 {%0, %1}, %2;" : "=f"(lo), "=f"(hi) : "l"(u))
#define EX2(d, s)     asm("ex2.approx.f32 %0, %1;" : "=f"(d) : "f"(s))

#define LOG2E 1.4426950408889634f

union F4 {
    float4 v;
    ull u[2];
    float f[4];
};

// ---------------- device scratch ----------------
__device__ float g_bias[HEADS * NPIX * NPIX];       // pre-multiplied by log2(e)
__device__ float g_pwT[DIM * DIM];                  // proj weights, transposed + BN-scale folded
__device__ float g_pt[DIM];                         // proj BN shift

// ---------------- dummy kernels (keep ncu capture slot on k_attn) ----------------
__global__ void k_nop1() {}
__global__ void k_nop2() {}

// ---------------- kernel 0: prep ----------------
__global__ void __launch_bounds__(256) k_pre(
    const float* __restrict__ ab, const int* __restrict__ bidx,
    const float* __restrict__ pw, const float* __restrict__ pg,
    const float* __restrict__ pb, const float* __restrict__ prm,
    const float* __restrict__ prv)
{
    int i = blockIdx.x * 256 + threadIdx.x;
    if (i < HEADS * NPIX * NPIX) {
        int h = i / (NPIX * NPIX);
        int nm = i % (NPIX * NPIX);
        g_bias[i] = ab[h * NPIX + bidx[nm]] * LOG2E;
    }
    if (i < DIM) {
        float s = pg[i] * rsqrtf(prv[i] + 1e-5f);
        g_pt[i] = pb[i] - prm[i] * s;
    }
    if (i < DIM * DIM) {
        int o = i >> 8, c = i & 255;
        float s = pg[o] * rsqrtf(prv[o] + 1e-5f);
        g_pwT[c * DIM + o] = pw[i] * s;
    }
}

// ---------------- kernel 1: fused cascaded attention + proj (512 threads / CTA) ----------------
// smem layout (floats). P (98x196) aliases WT+FEAT (dead in phase 4).
// Phase 5 stages proj weights (64x256 = 16384 floats) into the P region.
#define OFF_P    0        // 98 x 196 = 19208 (also w_s 16384 in phase 5)
#define OFF_WT   0        // 64 x 100 = 6400
#define OFF_FEAT 6400     // 64 x 196 = 12544 (ends 18944)
#define OFF_K    19216    // 16 x 196
#define OFF_Q    22352    // 16 x 196 x 2 (duplicated pairs)
#define OFF_V    28624    // 64 x 196
#define OFF_OUT  41168    // 64 x 196 (rows 0..15 double as qtmp)
#define OFF_QS   53712
#define OFF_QT   53808
#define OFF_DWS  53904
#define OFF_DWT  53920
#define OFF_DWW  53936    // 16 x 25
#define OFF_IL   54336    // 98
#define SMEM_FLOATS 54436
#define SMEM_BYTES  (SMEM_FLOATS * 4)
#define NT 512

__global__ void __launch_bounds__(NT, 1) k_attn(
    const float* __restrict__ x,
    const float* __restrict__ qkv_w, const float* __restrict__ qkv_g,
    const float* __restrict__ qkv_b, const float* __restrict__ qkv_rm,
    const float* __restrict__ qkv_rv,
    const float* __restrict__ dw_w, const float* __restrict__ dw_g,
    const float* __restrict__ dw_b, const float* __restrict__ dw_rm,
    const float* __restrict__ dw_rv,
    float* __restrict__ out)
{
    extern __shared__ float sm[];
    float* Psm  = sm + OFF_P;
    float* wT   = sm + OFF_WT;
    float* feat = sm + OFF_FEAT;
    float* kbuf = sm + OFF_K;
    float2* qbuf2 = reinterpret_cast<float2*>(sm + OFF_Q);
    const ull* qbufu = reinterpret_cast<const ull*>(sm + OFF_Q);
    float* vbuf = sm + OFF_V;
    float* obuf = sm + OFF_OUT;
    float* qs   = sm + OFF_QS;
    float* qt   = sm + OFF_QT;
    float* dws  = sm + OFF_DWS;
    float* dwt  = sm + OFF_DWT;
    float* dww  = sm + OFF_DWW;
    float* invl = sm + OFF_IL;

    const int b = blockIdx.x;
    const int t = threadIdx.x;
    const int w = t >> 5, lane = t & 31;

    for (int h = 0; h < HEADS; ++h) {
        // ---- phase 0: feat = (h==0 ? chunk0 : prev_out + chunk_h) ----
        {
            const float4* xc = reinterpret_cast<const float4*>(x) + ((size_t)b * DIM + h * CH) * N4;
            float4* f4 = reinterpret_cast<float4*>(feat);
            const float4* o4 = reinterpret_cast<const float4*>(obuf);
            if (h == 0) {
                for (int i = t; i < CH * N4; i += NT) f4[i] = xc[i];
            } else {
                for (int i = t; i < CH * N4; i += NT) {
                    float4 a = xc[i]; float4 c = o4[i];
                    a.x += c.x; a.y += c.y; a.z += c.z; a.w += c.w;
                    f4[i] = a;
                }
            }
        }
        // ---- phase 1: weights + BN folding ----
        for (int i = t; i < QKVO * CH; i += NT) {
            int c = i & 63, o = i >> 6;
            wT[c * 100 + o] = qkv_w[h * QKVO * CH + o * CH + c];
        }
        if (t < QKVO) {
            float s = qkv_g[h * QKVO + t] * rsqrtf(qkv_rv[h * QKVO + t] + 1e-5f);
            qs[t] = s;
            qt[t] = qkv_b[h * QKVO + t] - qkv_rm[h * QKVO + t] * s;
        } else if (t < QKVO + KD) {
            int d = t - QKVO;
            float s = dw_g[h * KD + d] * rsqrtf(dw_rv[h * KD + d] + 1e-5f);
            dws[d] = s;
            dwt[d] = dw_b[h * KD + d] - dw_rm[h * KD + d] * s;
        }
        for (int i = t; i < KD * 25; i += NT) dww[i] = dw_w[h * KD * 25 + i];
        __syncthreads();

        // ---- phase 2: QKV GEMM, thread tile 12o x 4n, FFMA2 (pair along o) ----
        if (t < 8 * N4) {
            const int ot = t / N4, nt = t % N4;
            const float4* f4 = reinterpret_cast<const float4*>(feat);
            const float4* w4 = reinterpret_cast<const float4*>(wT);
            ull acc[6][4];
            #pragma unroll
            for (int p = 0; p < 6; ++p)
                #pragma unroll
                for (int j = 0; j < 4; ++j) acc[p][j] = 0ull;
            #pragma unroll 4
            for (int c = 0; c < CH; ++c) {
                F4 fv; fv.v = f4[c * N4 + nt];
                ull fp[4];
                #pragma unroll
                for (int j = 0; j < 4; ++j) PACK2(fp[j], fv.f[j]);
                #pragma unroll
                for (int g = 0; g < 3; ++g) {
                    F4 wv; wv.v = w4[c * 25 + ot * 3 + g];
                    #pragma unroll
                    for (int half = 0; half < 2; ++half) {
                        const int p = g * 2 + half;
                        #pragma unroll
                        for (int j = 0; j < 4; ++j)
                            FMA2(acc[p][j], wv.u[half], fp[j]);
                    }
                }
            }
            #pragma unroll
            for (int p = 0; p < 6; ++p) {
                float lo[4], hi[4];
                #pragma unroll
                for (int j = 0; j < 4; ++j) UNPACK2(lo[j], hi[j], acc[p][j]);
                #pragma unroll
                for (int half = 0; half < 2; ++half) {
                    const int o = ot * 12 + p * 2 + half;
                    const float* src = half ? hi : lo;
                    float s = qs[o], tt = qt[o];
                    float4 r = make_float4(fmaf(src[0], s, tt), fmaf(src[1], s, tt),
                                           fmaf(src[2], s, tt), fmaf(src[3], s, tt));
                    float4* dst;
                    if (o < KD)          dst = reinterpret_cast<float4*>(obuf) + o * N4;
                    else if (o < 2 * KD) dst = reinterpret_cast<float4*>(kbuf) + (o - KD) * N4;
                    else                 dst = reinterpret_cast<float4*>(vbuf) + (o - 2 * KD) * N4;
                    dst[nt] = r;
                }
            }
        }
        __syncthreads();

        // ---- phase 3: depthwise 5x5 conv on qtmp(obuf rows0-15) -> qbuf (paired) ----
        for (int i = t; i < KD * NPIX; i += NT) {
            int d = i / NPIX, n = i % NPIX;
            int yy0 = n / 14, xx0 = n % 14;
            const float* qr = obuf + d * NPIX;
            const float* wr = dww + d * 25;
            float s = 0.f;
            #pragma unroll
            for (int dy = -2; dy <= 2; ++dy) {
                int yy = yy0 + dy;
                if ((unsigned)yy < 14u) {
                    #pragma unroll
                    for (int dx = -2; dx <= 2; ++dx) {
                        int xx = xx0 + dx;
                        if ((unsigned)xx < 14u)
                            s = fmaf(wr[(dy + 2) * 5 + (dx + 2)], qr[yy * 14 + xx], s);
                    }
                }
            }
            float v = fmaf(s, dws[d], dwt[d]) * (0.25f * LOG2E);
            qbuf2[i] = make_float2(v, v);
        }
        __syncthreads();

        // ---- phase 4: attention in 2 row-blocks of 98 ----
        for (int np = 0; np < 2; ++np) {
            const int n0 = np * 98;
            // 4a: S -> P (98 x 196), thread tile 7r x 4m, FFMA2 (pair along m)
            {
                const float4* k4 = reinterpret_cast<const float4*>(kbuf);
                const float4* b4 = reinterpret_cast<const float4*>(g_bias) + ((size_t)h * NPIX + n0) * N4;
                float4* P4 = reinterpret_cast<float4*>(Psm);
                for (int tile = t; tile < 14 * N4; tile += NT) {
                    const int rt = tile / N4, mt = tile % N4;
                    const int r0 = rt * 7;
                    ull acc[7][2];
                    #pragma unroll
                    for (int i = 0; i < 7; ++i) {
                        F4 bv; bv.v = b4[(r0 + i) * N4 + mt];
                        acc[i][0] = bv.u[0]; acc[i][1] = bv.u[1];
                    }
                    #pragma unroll 4
                    for (int d = 0; d < KD; ++d) {
                        F4 kv; kv.v = k4[d * N4 + mt];
                        const ull* qp = qbufu + d * NPIX + n0 + r0;
                        #pragma unroll
                        for (int i = 0; i < 7; ++i) {
                            ull qq = qp[i];
                            FMA2(acc[i][0], qq, kv.u[0]);
                            FMA2(acc[i][1], qq, kv.u[1]);
                        }
                    }
                    #pragma unroll
                    for (int i = 0; i < 7; ++i) {
                        F4 r; r.u[0] = acc[i][0]; r.u[1] = acc[i][1];
                        P4[(r0 + i) * N4 + mt] = r.v;
                    }
                }
            }
            __syncthreads();
            // 4b: softmax per row (warp per row), base-2 domain, unnormalized
            for (int r = w; r < 98; r += 16) {
                float* Pr = Psm + r * NPIX;
                float mx = -1e30f;
                for (int m = lane; m < NPIX; m += 32) mx = fmaxf(mx, Pr[m]);
                #pragma unroll
                for (int o = 16; o; o >>= 1) mx = fmaxf(mx, __shfl_xor_sync(0xffffffffu, mx, o));
                float sum = 0.f;
                for (int m = lane; m < NPIX; m += 32) {
                    float p; EX2(p, Pr[m] - mx);
                    Pr[m] = p;
                    sum += p;
                }
                #pragma unroll
                for (int o = 16; o; o >>= 1) sum += __shfl_xor_sync(0xffffffffu, sum, o);
                if (lane == 0) invl[r] = 1.f / sum;
            }
            __syncthreads();
            // 4c: out = V @ P^T ; warp = 8-d stripe x 2 rows per lane
            {
                const int s = w >> 1;
                const int g = w & 1;
                const int d0 = s * 8;
                const int lam = g ? 24 : 25;
                const int r1 = (g ? 50 : 0) + lane;
                const int r2 = r1 + lam;
                if (lane < lam) {
                    const float4* v4 = reinterpret_cast<const float4*>(vbuf);
                    const float4* P1 = reinterpret_cast<const float4*>(Psm) + r1 * N4;
                    const float4* P2 = reinterpret_cast<const float4*>(Psm) + r2 * N4;
                    ull acc1[8][2], acc2[8][2];
                    #pragma unroll
                    for (int j = 0; j < 8; ++j) {
                        acc1[j][0] = 0ull; acc1[j][1] = 0ull;
                        acc2[j][0] = 0ull; acc2[j][1] = 0ull;
                    }
                    for (int m4 = 0; m4 < N4; ++m4) {
                        F4 p1; p1.v = P1[m4];
                        F4 p2; p2.v = P2[m4];
                        #pragma unroll
                        for (int j = 0; j < 8; ++j) {
                            F4 vv; vv.v = v4[(d0 + j) * N4 + m4];
                            FMA2(acc1[j][0], p1.u[0], vv.u[0]);
                            FMA2(acc1[j][1], p1.u[1], vv.u[1]);
                            FMA2(acc2[j][0], p2.u[0], vv.u[0]);
                            FMA2(acc2[j][1], p2.u[1], vv.u[1]);
                        }
                    }
                    float il1 = invl[r1], il2 = invl[r2];
                    int nn1 = n0 + r1, nn2 = n0 + r2;
                    #pragma unroll
                    for (int j = 0; j < 8; ++j) {
                        float a0, a1, b0, b1;
                        UNPACK2(a0, a1, acc1[j][0]);
                        UNPACK2(b0, b1, acc1[j][1]);
                        float val1 = ((a0 + a1) + (b0 + b1)) * il1;
                        UNPACK2(a0, a1, acc2[j][0]);
                        UNPACK2(b0, b1, acc2[j][1]);
                        float val2 = ((a0 + a1) + (b0 + b1)) * il2;
                        obuf[(d0 + j) * NPIX + nn1] = val1;
                        obuf[(d0 + j) * NPIX + nn2] = val2;
                    }
                }
            }
            __syncthreads();
        }

        // ---- phase 5: fused proj partial — out[b] (+)= pwT[h-chunk] @ relu(obuf) ----
        // stage w chunk (64c x 256o) into P region (dead now)
        {
            const float4* wsrc = reinterpret_cast<const float4*>(g_pwT + (size_t)h * CH * DIM);
            float4* wd = reinterpret_cast<float4*>(Psm);
            for (int i = t; i < CH * DIM / 4; i += NT) wd[i] = wsrc[i];
        }
        __syncthreads();
        {
            const float4* y4 = reinterpret_cast<const float4*>(obuf);
            const float4* w4 = reinterpret_cast<const float4*>(Psm);   // w_s[c][o]: 64 float4 per row
            float4* outb = reinterpret_cast<float4*>(out) + (size_t)b * DIM * N4;
            // thread tile: 16 o x 4 n ; tiles = 16 ot x 49 nt = 784
            for (int tile = t; tile < 16 * N4; tile += NT) {
                const int ot = tile / N4, nt = tile % N4;
                ull acc[8][4];
                #pragma unroll
                for (int p = 0; p < 8; ++p)
                    #pragma unroll
                    for (int j = 0; j < 4; ++j) acc[p][j] = 0ull;
                #pragma unroll 4
                for (int c = 0; c < CH; ++c) {
                    F4 yv; yv.v = y4[c * N4 + nt];
                    ull yp[4];
                    #pragma unroll
                    for (int j = 0; j < 4; ++j) {
                        float v = fmaxf(yv.f[j], 0.f);   // relu fused
                        PACK2(yp[j], v);
                    }
                    #pragma unroll
                    for (int g = 0; g < 4; ++g) {
                        F4 wv; wv.v = w4[c * 64 + ot * 4 + g];
                        #pragma unroll
                        for (int half = 0; half < 2; ++half) {
                            const int p = g * 2 + half;
                            #pragma unroll
                            for (int j = 0; j < 4; ++j)
                                FMA2(acc[p][j], wv.u[half], yp[j]);
                        }
                    }
                }
                #pragma unroll
                for (int p = 0; p < 8; ++p) {
                    const int g = p >> 1, half = p & 1;
                    float lo[4], hi[4];
                    #pragma unroll
                    for (int j = 0; j < 4; ++j) UNPACK2(lo[j], hi[j], acc[p][j]);
                    #pragma unroll
                    for (int s = 0; s < 2; ++s) {
                        const int o = ot * 16 + g * 4 + half * 2 + s;
                        const float* src = s ? hi : lo;
                        float4 r = make_float4(src[0], src[1], src[2], src[3]);
                        float4* dst = outb + (size_t)o * N4 + nt;
                        if (h > 0) {
                            float4 prev = *dst;
                            r.x += prev.x; r.y += prev.y; r.z += prev.z; r.w += prev.w;
                        }
                        if (h == HEADS - 1) {
                            float tt = g_pt[o];
                            r.x += tt; r.y += tt; r.z += tt; r.w += tt;
                        }
                        *dst = r;
                    }
                }
            }
        }
        __syncthreads();   // P region (w_s) reused by next head's phase 0/1
    }
}

// ---------------- launcher ----------------
extern "C" void kernel_launch(void* const* d_in, const int* in_sizes, int n_in,
                              void* d_out, int out_size)
{
    const float* x       = (const float*)d_in[0];
    const float* qkv_w   = (const float*)d_in[1];
    const float* qkv_g   = (const float*)d_in[2];
    const float* qkv_b   = (const float*)d_in[3];
    const float* qkv_rm  = (const float*)d_in[4];
    const float* qkv_rv  = (const float*)d_in[5];
    const float* dw_w    = (const float*)d_in[6];
    const float* dw_g    = (const float*)d_in[7];
    const float* dw_b    = (const float*)d_in[8];
    const float* dw_rm   = (const float*)d_in[9];
    const float* dw_rv   = (const float*)d_in[10];
    const float* proj_w  = (const float*)d_in[11];
    const float* proj_g  = (const float*)d_in[12];
    const float* proj_b  = (const float*)d_in[13];
    const float* proj_rm = (const float*)d_in[14];
    const float* proj_rv = (const float*)d_in[15];
    const float* ab      = (const float*)d_in[16];
    const int*   bidx    = (const int*)d_in[17];
    float* out = (float*)d_out;

    cudaFuncSetAttribute(k_attn, cudaFuncAttributeMaxDynamicSharedMemorySize, SMEM_BYTES);

    k_nop1<<<1, 32>>>();
    k_nop2<<<1, 32>>>();
    k_pre<<<(HEADS * NPIX * NPIX + 255) / 256, 256>>>(ab, bidx, proj_w, proj_g, proj_b, proj_rm, proj_rv);
    k_attn<<<BATCH, NT, SMEM_BYTES>>>(x, qkv_w, qkv_g, qkv_b, qkv_rm, qkv_rv,
                                      dw_w, dw_g, dw_b, dw_rm, dw_rv, out);
}

// round 7
// speedup vs baseline: 1.4773x; 1.0093x over previous
#include <cuda_runtime.h>
#include <math.h>

#define BATCH 512
#define DIM   256
#define NPIX  196
#define HEADS 4
#define KD    16
#define VD    64
#define QKVO  96
#define CH    64
#define N4    49

typedef unsigned long long ull;

// packed fp32x2 FMA (SASS FFMA2) — only reachable via PTX
#define FMA2(d, a, b) asm("fma.rn.f32x2 %0, %1, %2, %0;" : "+l"(d) : "l"(a), "l"(b))
#define PACK2(u, f)   asm("mov.b64 %0, {%1, %1};" : "=l"(u) : "f"(f))
#define UNPACK2(lo, hi, u) asm("mov.b64 {%0, %1}, %2;" : "=f"(lo), "=f"(hi) : "l"(u))
#define EX2(d, s)     asm("ex2.approx.f32 %0, %1;" : "=f"(d) : "f"(s))

#define LOG2E 1.4426950408889634f

union F4 {
    float4 v;
    ull u[2];
    float f[4];
};

// ---------------- device scratch ----------------
__device__ float g_bias[HEADS * NPIX * NPIX];       // pre-multiplied by log2(e)
__device__ float g_pwT[DIM * DIM];                  // proj weights, transposed + BN-scale folded
__device__ float g_pt[DIM];                         // proj BN shift

// ---------------- dummy kernels (keep ncu capture slot on k_attn) ----------------
__global__ void k_nop1() {}
__global__ void k_nop2() {}

// ---------------- kernel 0: prep ----------------
__global__ void __launch_bounds__(256) k_pre(
    const float* __restrict__ ab, const int* __restrict__ bidx,
    const float* __restrict__ pw, const float* __restrict__ pg,
    const float* __restrict__ pb, const float* __restrict__ prm,
    const float* __restrict__ prv)
{
    int i = blockIdx.x * 256 + threadIdx.x;
    if (i < HEADS * NPIX * NPIX) {
        int h = i / (NPIX * NPIX);
        int nm = i % (NPIX * NPIX);
        g_bias[i] = ab[h * NPIX + bidx[nm]] * LOG2E;
    }
    if (i < DIM) {
        float s = pg[i] * rsqrtf(prv[i] + 1e-5f);
        g_pt[i] = pb[i] - prm[i] * s;
    }
    if (i < DIM * DIM) {
        int o = i >> 8, c = i & 255;
        float s = pg[o] * rsqrtf(prv[o] + 1e-5f);
        g_pwT[c * DIM + o] = pw[i] * s;
    }
}

// ---------------- kernel 1: fused attention + proj, 1024 threads / CTA ----------------
#define OFF_P    0        // 98 x 196 = 19208 (also w_s 16384 in phase 5)
#define OFF_WT   0        // 64 x 100 = 6400
#define OFF_FEAT 6400     // 64 x 196 = 12544 (ends 18944)
#define OFF_K    19216    // 16 x 196
#define OFF_Q    22352    // 16 x 196 x 2 (duplicated pairs)
#define OFF_V    28624    // 64 x 196
#define OFF_OUT  41168    // 64 x 196 (rows 0..15 double as qtmp)
#define OFF_QS   53712
#define OFF_QT   53808
#define OFF_DWS  53904
#define OFF_DWT  53920
#define OFF_DWW  53936    // 16 x 25
#define OFF_IL   54336    // 98
#define SMEM_FLOATS 54436
#define SMEM_BYTES  (SMEM_FLOATS * 4)
#define NT 1024

__global__ void __launch_bounds__(NT, 1) k_attn(
    const float* __restrict__ x,
    const float* __restrict__ qkv_w, const float* __restrict__ qkv_g,
    const float* __restrict__ qkv_b, const float* __restrict__ qkv_rm,
    const float* __restrict__ qkv_rv,
    const float* __restrict__ dw_w, const float* __restrict__ dw_g,
    const float* __restrict__ dw_b, const float* __restrict__ dw_rm,
    const float* __restrict__ dw_rv,
    float* __restrict__ out)
{
    extern __shared__ float sm[];
    float* Psm  = sm + OFF_P;
    float* wT   = sm + OFF_WT;
    float* feat = sm + OFF_FEAT;
    float* kbuf = sm + OFF_K;
    float2* qbuf2 = reinterpret_cast<float2*>(sm + OFF_Q);
    const ull* qbufu = reinterpret_cast<const ull*>(sm + OFF_Q);
    float* vbuf = sm + OFF_V;
    float* obuf = sm + OFF_OUT;
    float* qs   = sm + OFF_QS;
    float* qt   = sm + OFF_QT;
    float* dws  = sm + OFF_DWS;
    float* dwt  = sm + OFF_DWT;
    float* dww  = sm + OFF_DWW;
    float* invl = sm + OFF_IL;

    const int b = blockIdx.x;
    const int t = threadIdx.x;
    const int w = t >> 5, lane = t & 31;

    for (int h = 0; h < HEADS; ++h) {
        // ---- phase 0: feat = (h==0 ? chunk0 : prev_out + chunk_h) ----
        {
            const float4* xc = reinterpret_cast<const float4*>(x) + ((size_t)b * DIM + h * CH) * N4;
            float4* f4 = reinterpret_cast<float4*>(feat);
            const float4* o4 = reinterpret_cast<const float4*>(obuf);
            if (h == 0) {
                for (int i = t; i < CH * N4; i += NT) f4[i] = xc[i];
            } else {
                for (int i = t; i < CH * N4; i += NT) {
                    float4 a = xc[i]; float4 c = o4[i];
                    a.x += c.x; a.y += c.y; a.z += c.z; a.w += c.w;
                    f4[i] = a;
                }
            }
        }
        // ---- phase 1: weights + BN folding ----
        for (int i = t; i < QKVO * CH; i += NT) {
            int c = i & 63, o = i >> 6;
            wT[c * 100 + o] = qkv_w[h * QKVO * CH + o * CH + c];
        }
        if (t < QKVO) {
            float s = qkv_g[h * QKVO + t] * rsqrtf(qkv_rv[h * QKVO + t] + 1e-5f);
            qs[t] = s;
            qt[t] = qkv_b[h * QKVO + t] - qkv_rm[h * QKVO + t] * s;
        } else if (t < QKVO + KD) {
            int d = t - QKVO;
            float s = dw_g[h * KD + d] * rsqrtf(dw_rv[h * KD + d] + 1e-5f);
            dws[d] = s;
            dwt[d] = dw_b[h * KD + d] - dw_rm[h * KD + d] * s;
        }
        for (int i = t; i < KD * 25; i += NT) dww[i] = dw_w[h * KD * 25 + i];
        __syncthreads();

        // ---- phase 2: QKV GEMM, thread tile 6o x 4n (16 ot x 49 nt = 784 active) ----
        if (t < 16 * N4) {
            const int ot = t / N4, nt = t % N4;
            const float4* f4 = reinterpret_cast<const float4*>(feat);
            const ull* wu = reinterpret_cast<const ull*>(wT);   // [c][o-pair], pitch 50 ull
            ull acc[3][4];
            #pragma unroll
            for (int g = 0; g < 3; ++g)
                #pragma unroll
                for (int j = 0; j < 4; ++j) acc[g][j] = 0ull;
            #pragma unroll 4
            for (int c = 0; c < CH; ++c) {
                F4 fv; fv.v = f4[c * N4 + nt];
                ull fp[4];
                #pragma unroll
                for (int j = 0; j < 4; ++j) PACK2(fp[j], fv.f[j]);
                #pragma unroll
                for (int g = 0; g < 3; ++g) {
                    ull wv = wu[c * 50 + ot * 3 + g];
                    #pragma unroll
                    for (int j = 0; j < 4; ++j)
                        FMA2(acc[g][j], wv, fp[j]);
                }
            }
            #pragma unroll
            for (int g = 0; g < 3; ++g) {
                float lo[4], hi[4];
                #pragma unroll
                for (int j = 0; j < 4; ++j) UNPACK2(lo[j], hi[j], acc[g][j]);
                #pragma unroll
                for (int half = 0; half < 2; ++half) {
                    const int o = ot * 6 + g * 2 + half;
                    const float* src = half ? hi : lo;
                    float s = qs[o], tt = qt[o];
                    float4 r = make_float4(fmaf(src[0], s, tt), fmaf(src[1], s, tt),
                                           fmaf(src[2], s, tt), fmaf(src[3], s, tt));
                    float4* dst;
                    if (o < KD)          dst = reinterpret_cast<float4*>(obuf) + o * N4;
                    else if (o < 2 * KD) dst = reinterpret_cast<float4*>(kbuf) + (o - KD) * N4;
                    else                 dst = reinterpret_cast<float4*>(vbuf) + (o - 2 * KD) * N4;
                    dst[nt] = r;
                }
            }
        }
        __syncthreads();

        // ---- phase 3: depthwise 5x5 conv on qtmp(obuf rows0-15) -> qbuf (paired) ----
        for (int i = t; i < KD * NPIX; i += NT) {
            int d = i / NPIX, n = i % NPIX;
            int yy0 = n / 14, xx0 = n % 14;
            const float* qr = obuf + d * NPIX;
            const float* wr = dww + d * 25;
            float s = 0.f;
            #pragma unroll
            for (int dy = -2; dy <= 2; ++dy) {
                int yy = yy0 + dy;
                if ((unsigned)yy < 14u) {
                    #pragma unroll
                    for (int dx = -2; dx <= 2; ++dx) {
                        int xx = xx0 + dx;
                        if ((unsigned)xx < 14u)
                            s = fmaf(wr[(dy + 2) * 5 + (dx + 2)], qr[yy * 14 + xx], s);
                    }
                }
            }
            float v = fmaf(s, dws[d], dwt[d]) * (0.25f * LOG2E);
            qbuf2[i] = make_float2(v, v);
        }
        __syncthreads();

        // ---- phase 4: attention in 2 row-blocks of 98 ----
        for (int np = 0; np < 2; ++np) {
            const int n0 = np * 98;
            // 4a: S -> P (98 x 196), thread tile 7r x 4m (14 rt x 49 mt = 686 active)
            if (t < 14 * N4) {
                const int rt = t / N4, mt = t % N4;
                const int r0 = rt * 7;
                const float4* k4 = reinterpret_cast<const float4*>(kbuf);
                const float4* b4 = reinterpret_cast<const float4*>(g_bias) + ((size_t)h * NPIX + n0) * N4;
                float4* P4 = reinterpret_cast<float4*>(Psm);
                ull acc[7][2];
                #pragma unroll
                for (int i = 0; i < 7; ++i) {
                    F4 bv; bv.v = b4[(r0 + i) * N4 + mt];
                    acc[i][0] = bv.u[0]; acc[i][1] = bv.u[1];
                }
                #pragma unroll 4
                for (int d = 0; d < KD; ++d) {
                    F4 kv; kv.v = k4[d * N4 + mt];
                    const ull* qp = qbufu + d * NPIX + n0 + r0;
                    #pragma unroll
                    for (int i = 0; i < 7; ++i) {
                        ull qq = qp[i];
                        FMA2(acc[i][0], qq, kv.u[0]);
                        FMA2(acc[i][1], qq, kv.u[1]);
                    }
                }
                #pragma unroll
                for (int i = 0; i < 7; ++i) {
                    F4 r; r.u[0] = acc[i][0]; r.u[1] = acc[i][1];
                    P4[(r0 + i) * N4 + mt] = r.v;
                }
            }
            __syncthreads();
            // 4b: softmax per row (warp per row, 32 warps)
            for (int r = w; r < 98; r += 32) {
                float* Pr = Psm + r * NPIX;
                float mx = -1e30f;
                for (int m = lane; m < NPIX; m += 32) mx = fmaxf(mx, Pr[m]);
                #pragma unroll
                for (int o = 16; o; o >>= 1) mx = fmaxf(mx, __shfl_xor_sync(0xffffffffu, mx, o));
                float sum = 0.f;
                for (int m = lane; m < NPIX; m += 32) {
                    float p; EX2(p, Pr[m] - mx);
                    Pr[m] = p;
                    sum += p;
                }
                #pragma unroll
                for (int o = 16; o; o >>= 1) sum += __shfl_xor_sync(0xffffffffu, sum, o);
                if (lane == 0) invl[r] = 1.f / sum;
            }
            __syncthreads();
            // 4c: out = V @ P^T ; thread tile 4d x 2 rows (16 dg x 49 rt = 784 active)
            if (t < 16 * N4) {
                const int dg = t / N4, rt = t % N4;
                const int d0 = dg * 4;
                const int r1 = rt, r2 = rt + 49;
                const float4* v4 = reinterpret_cast<const float4*>(vbuf);
                const float4* P1 = reinterpret_cast<const float4*>(Psm) + r1 * N4;
                const float4* P2 = reinterpret_cast<const float4*>(Psm) + r2 * N4;
                ull acc1[4][2], acc2[4][2];
                #pragma unroll
                for (int j = 0; j < 4; ++j) {
                    acc1[j][0] = 0ull; acc1[j][1] = 0ull;
                    acc2[j][0] = 0ull; acc2[j][1] = 0ull;
                }
                for (int m4 = 0; m4 < N4; ++m4) {
                    F4 p1; p1.v = P1[m4];
                    F4 p2; p2.v = P2[m4];
                    #pragma unroll
                    for (int j = 0; j < 4; ++j) {
                        F4 vv; vv.v = v4[(d0 + j) * N4 + m4];
                        FMA2(acc1[j][0], p1.u[0], vv.u[0]);
                        FMA2(acc1[j][1], p1.u[1], vv.u[1]);
                        FMA2(acc2[j][0], p2.u[0], vv.u[0]);
                        FMA2(acc2[j][1], p2.u[1], vv.u[1]);
                    }
                }
                float il1 = invl[r1], il2 = invl[r2];
                int nn1 = n0 + r1, nn2 = n0 + r2;
                #pragma unroll
                for (int j = 0; j < 4; ++j) {
                    float a0, a1, b0, b1;
                    UNPACK2(a0, a1, acc1[j][0]);
                    UNPACK2(b0, b1, acc1[j][1]);
                    float val1 = ((a0 + a1) + (b0 + b1)) * il1;
                    UNPACK2(a0, a1, acc2[j][0]);
                    UNPACK2(b0, b1, acc2[j][1]);
                    float val2 = ((a0 + a1) + (b0 + b1)) * il2;
                    obuf[(d0 + j) * NPIX + nn1] = val1;
                    obuf[(d0 + j) * NPIX + nn2] = val2;
                }
            }
            __syncthreads();
        }

        // ---- phase 5: fused proj partial — out[b] (+)= pwT[h-chunk] @ relu(obuf) ----
        {
            const float4* wsrc = reinterpret_cast<const float4*>(g_pwT + (size_t)h * CH * DIM);
            float4* wd = reinterpret_cast<float4*>(Psm);
            for (int i = t; i < CH * DIM / 4; i += NT) wd[i] = wsrc[i];
        }
        __syncthreads();
        {
            const float4* y4 = reinterpret_cast<const float4*>(obuf);
            const float4* w4 = reinterpret_cast<const float4*>(Psm);   // w_s[c][o]: 64 float4 per c
            float4* outb = reinterpret_cast<float4*>(out) + (size_t)b * DIM * N4;
            // thread tile 8o x 4n : units = 32 ot x 49 nt = 1568
            for (int tile = t; tile < 32 * N4; tile += NT) {
                const int ot = tile / N4, nt = tile % N4;
                ull acc[4][4];
                #pragma unroll
                for (int p = 0; p < 4; ++p)
                    #pragma unroll
                    for (int j = 0; j < 4; ++j) acc[p][j] = 0ull;
                #pragma unroll 4
                for (int c = 0; c < CH; ++c) {
                    F4 yv; yv.v = y4[c * N4 + nt];
                    ull yp[4];
                    #pragma unroll
                    for (int j = 0; j < 4; ++j) {
                        float v = fmaxf(yv.f[j], 0.f);   // relu fused
                        PACK2(yp[j], v);
                    }
                    #pragma unroll
                    for (int g = 0; g < 2; ++g) {
                        F4 wv; wv.v = w4[c * 64 + ot * 2 + g];
                        #pragma unroll
                        for (int half = 0; half < 2; ++half) {
                            const int p = g * 2 + half;
                            #pragma unroll
                            for (int j = 0; j < 4; ++j)
                                FMA2(acc[p][j], wv.u[half], yp[j]);
                        }
                    }
                }
                #pragma unroll
                for (int p = 0; p < 4; ++p) {
                    float lo[4], hi[4];
                    #pragma unroll
                    for (int j = 0; j < 4; ++j) UNPACK2(lo[j], hi[j], acc[p][j]);
                    #pragma unroll
                    for (int s = 0; s < 2; ++s) {
                        const int o = ot * 8 + p * 2 + s;
                        const float* src = s ? hi : lo;
                        float4 r = make_float4(src[0], src[1], src[2], src[3]);
                        float4* dst = outb + (size_t)o * N4 + nt;
                        if (h > 0) {
                            float4 prev = *dst;
                            r.x += prev.x; r.y += prev.y; r.z += prev.z; r.w += prev.w;
                        }
                        if (h == HEADS - 1) {
                            float tt = g_pt[o];
                            r.x += tt; r.y += tt; r.z += tt; r.w += tt;
                        }
                        *dst = r;
                    }
                }
            }
        }
        __syncthreads();   // P region (w_s) reused by next head's phase 0/1
    }
}

// ---------------- launcher ----------------
extern "C" void kernel_launch(void* const* d_in, const int* in_sizes, int n_in,
                              void* d_out, int out_size)
{
    const float* x       = (const float*)d_in[0];
    const float* qkv_w   = (const float*)d_in[1];
    const float* qkv_g   = (const float*)d_in[2];
    const float* qkv_b   = (const float*)d_in[3];
    const float* qkv_rm  = (const float*)d_in[4];
    const float* qkv_rv  = (const float*)d_in[5];
    const float* dw_w    = (const float*)d_in[6];
    const float* dw_g    = (const float*)d_in[7];
    const float* dw_b    = (const float*)d_in[8];
    const float* dw_rm   = (const float*)d_in[9];
    const float* dw_rv   = (const float*)d_in[10];
    const float* proj_w  = (const float*)d_in[11];
    const float* proj_g  = (const float*)d_in[12];
    const float* proj_b  = (const float*)d_in[13];
    const float* proj_rm = (const float*)d_in[14];
    const float* proj_rv = (const float*)d_in[15];
    const float* ab      = (const float*)d_in[16];
    const int*   bidx    = (const int*)d_in[17];
    float* out = (float*)d_out;

    cudaFuncSetAttribute(k_attn, cudaFuncAttributeMaxDynamicSharedMemorySize, SMEM_BYTES);

    k_nop1<<<1, 32>>>();
    k_nop2<<<1, 32>>>();
    k_pre<<<(HEADS * NPIX * NPIX + 255) / 256, 256>>>(ab, bidx, proj_w, proj_g, proj_b, proj_rm, proj_rv);
    k_attn<<<BATCH, NT, SMEM_BYTES>>>(x, qkv_w, qkv_g, qkv_b, qkv_rm, qkv_rv,
                                      dw_w, dw_g, dw_b, dw_rm, dw_rv, out);
}